// round 1
// baseline (speedup 1.0000x reference)
#include <cuda_runtime.h>
#include <cuda_bf16.h>
#include <cstdint>

// Problem constants (MambaSSMBlock: B=2, L=2048, d_model=1024, d_inner=2048,
// d_state=16, d_conv=4, dt_rank=64)
#define BB      2
#define LL      2048
#define DMODEL  1024
#define DINNER  2048
#define DSTATE  16
#define DTRANK  64
#define NROWS   (BB * LL)          // 4096
#define XDBL_W  (DTRANK + 2 * DSTATE)  // 96

// ---------------- scratch (static device globals; no allocs) ----------------
__device__ float d_xz  [(size_t)NROWS * (2 * DINNER)];  // in_proj output [4096,4096]
__device__ float d_xs  [(size_t)NROWS * DINNER];        // conv+silu      [4096,2048]
__device__ float d_xdbl[(size_t)NROWS * XDBL_W];        // dt_raw|B|C     [4096,96]
__device__ float d_dt  [(size_t)NROWS * DINNER];        // softplus dt    [4096,2048]
__device__ float d_y   [(size_t)NROWS * DINNER];        // scan output    [4096,2048]
__device__ float d_tmp [(size_t)NROWS * DMODEL];        // after W_out_ssm[4096,1024]
__device__ float d_A   [DINNER * DSTATE];               // A = -exp(A_log)

// ---------------- helpers ----------------
__device__ __forceinline__ float silu_f(float v) {
    return v / (1.f + __expf(-v));
}

// ---------------- A = -exp(A_log) ----------------
__global__ void prep_A_kernel(const float* __restrict__ A_log) {
    int i = blockIdx.x * blockDim.x + threadIdx.x;
    if (i < DINNER * DSTATE) d_A[i] = -expf(A_log[i]);
}

// ---------------- generic tiled GEMM: C[M,N] = A[M,K] @ W[N,K]^T (+epi) ------
// EPI: 0 = none, 1 = +bias, 2 = softplus(v + bias)
#define BM 128
#define BN 128
#define BK 16

template <int EPI>
__global__ void __launch_bounds__(256)
gemm_nt(const float* __restrict__ A, const float* __restrict__ W,
        const float* __restrict__ bias, float* __restrict__ C,
        int M, int N, int K, int lda, int ldc)
{
    __shared__ float As[BK][BM + 4];
    __shared__ float Bs[BK][BN + 4];
    const int tid = threadIdx.x;
    const int bm = blockIdx.y, bn = blockIdx.x;
    const int tx = tid & 15, ty = tid >> 4;

    float acc[8][8];
#pragma unroll
    for (int i = 0; i < 8; i++)
#pragma unroll
        for (int j = 0; j < 8; j++) acc[i][j] = 0.f;

    const float* Ablk = A + (size_t)bm * BM * lda;

    const int nk = K / BK;
    for (int kt = 0; kt < nk; kt++) {
        const int k0 = kt * BK;
#pragma unroll
        for (int i = 0; i < 2; i++) {
            int idx = tid + i * 256;
            int r   = idx >> 2;
            int kc  = (idx & 3) << 2;
            float4 av = *(const float4*)(Ablk + (size_t)r * lda + k0 + kc);
            As[kc + 0][r] = av.x; As[kc + 1][r] = av.y;
            As[kc + 2][r] = av.z; As[kc + 3][r] = av.w;
            int n = bn * BN + r;
            float4 wv = make_float4(0.f, 0.f, 0.f, 0.f);
            if (n < N) wv = *(const float4*)(W + (size_t)n * K + k0 + kc);
            Bs[kc + 0][r] = wv.x; Bs[kc + 1][r] = wv.y;
            Bs[kc + 2][r] = wv.z; Bs[kc + 3][r] = wv.w;
        }
        __syncthreads();
#pragma unroll
        for (int kk = 0; kk < BK; kk++) {
            float a[8], b[8];
            *(float4*)&a[0] = *(const float4*)&As[kk][ty * 8];
            *(float4*)&a[4] = *(const float4*)&As[kk][ty * 8 + 4];
            *(float4*)&b[0] = *(const float4*)&Bs[kk][tx * 8];
            *(float4*)&b[4] = *(const float4*)&Bs[kk][tx * 8 + 4];
#pragma unroll
            for (int i = 0; i < 8; i++)
#pragma unroll
                for (int j = 0; j < 8; j++)
                    acc[i][j] = fmaf(a[i], b[j], acc[i][j]);
        }
        __syncthreads();
    }

    const int n0 = bn * BN + tx * 8;
    if (n0 < N) {
        float bv[8];
        if (EPI >= 1) {
#pragma unroll
            for (int j = 0; j < 8; j++) bv[j] = bias[n0 + j];
        }
#pragma unroll
        for (int i = 0; i < 8; i++) {
            int m = bm * BM + ty * 8 + i;
            float out[8];
#pragma unroll
            for (int j = 0; j < 8; j++) {
                float v = acc[i][j];
                if (EPI >= 1) v += bv[j];
                if (EPI == 2) v = (v > 20.f) ? v : log1pf(__expf(v));
                out[j] = v;
            }
            *(float4*)(C + (size_t)m * ldc + n0)     = *(float4*)&out[0];
            *(float4*)(C + (size_t)m * ldc + n0 + 4) = *(float4*)&out[4];
        }
    }
}

// ---------------- causal depthwise conv (k=4) + SiLU ----------------
// reads xin = d_xz[:, 0:DINNER] (row stride 2*DINNER), writes d_xs [4096,2048]
__global__ void __launch_bounds__(256)
conv_silu_kernel(const float* __restrict__ conv_w, const float* __restrict__ conv_b)
{
    int idx = blockIdx.x * blockDim.x + threadIdx.x;   // NROWS * DINNER
    int d     = idx & (DINNER - 1);
    int rowid = idx >> 11;                              // b*L + l
    int l     = rowid & (LL - 1);
    const float* base = d_xz + (size_t)rowid * (2 * DINNER) + d;
    const float4 w = *(const float4*)(conv_w + d * 4);
    float acc = conv_b[d];
    if (l >= 3) acc = fmaf(w.x, base[-3 * (2 * DINNER)], acc);
    if (l >= 2) acc = fmaf(w.y, base[-2 * (2 * DINNER)], acc);
    if (l >= 1) acc = fmaf(w.z, base[-1 * (2 * DINNER)], acc);
    acc = fmaf(w.w, base[0], acc);
    d_xs[(size_t)rowid * DINNER + d] = silu_f(acc);
}

// ---------------- fused selective scan + D skip + gate ----------------
// one thread per (channel, state): 4096 channels x 16 states = 65536 threads.
// block = 256 threads = 16 channels (all same batch b).
__global__ void __launch_bounds__(256)
scan_kernel(const float* __restrict__ Dvec)
{
    const int s    = threadIdx.x & 15;          // state
    const int cloc = threadIdx.x >> 4;          // local channel 0..15
    const int b    = blockIdx.x >> 7;           // 256 blocks: 128 per batch
    const int d    = ((blockIdx.x & 127) << 4) + cloc;

    const float Aval = d_A[d * DSTATE + s];
    const float Dv   = Dvec[d];

    const float* dt_p = d_dt   + (size_t)b * LL * DINNER + d;
    const float* xs_p = d_xs   + (size_t)b * LL * DINNER + d;
    const float* z_p  = d_xz   + (size_t)b * LL * (2 * DINNER) + DINNER + d;
    const float* bc_p = d_xdbl + (size_t)b * LL * XDBL_W + DTRANK + s;
    float*       y_p  = d_y    + (size_t)b * LL * DINNER + d;

    float h = 0.f;
#pragma unroll 4
    for (int l = 0; l < LL; l++) {
        float dtv = __ldg(dt_p);
        float xv  = __ldg(xs_p);
        float Bv  = __ldg(bc_p);
        float Cv  = __ldg(bc_p + DSTATE);
        float a = __expf(dtv * Aval);
        h = fmaf(h, a, dtv * xv * Bv);
        float p = h * Cv;
        p += __shfl_xor_sync(0xffffffffu, p, 8);
        p += __shfl_xor_sync(0xffffffffu, p, 4);
        p += __shfl_xor_sync(0xffffffffu, p, 2);
        p += __shfl_xor_sync(0xffffffffu, p, 1);
        if (s == 0) {
            float zv = __ldg(z_p);
            y_p[0] = (p + xv * Dv) * silu_f(zv);
        }
        dt_p += DINNER; xs_p += DINNER; z_p += 2 * DINNER;
        bc_p += XDBL_W; y_p += DINNER;
    }
}

// ---------------- launch ----------------
extern "C" void kernel_launch(void* const* d_in, const int* in_sizes, int n_in,
                              void* d_out, int out_size)
{
    const float* x         = (const float*)d_in[0];
    const float* W_in      = (const float*)d_in[1];
    const float* conv_w    = (const float*)d_in[2];
    const float* conv_b    = (const float*)d_in[3];
    const float* W_xp      = (const float*)d_in[4];
    const float* W_dt      = (const float*)d_in[5];
    const float* b_dt      = (const float*)d_in[6];
    const float* A_log     = (const float*)d_in[7];
    const float* Dvec      = (const float*)d_in[8];
    const float* W_out_ssm = (const float*)d_in[9];
    const float* W_out     = (const float*)d_in[10];
    const float* b_out     = (const float*)d_in[11];
    float* out = (float*)d_out;

    float *xz, *xs, *xdbl, *dt, *y, *tmp;
    cudaGetSymbolAddress((void**)&xz,   d_xz);
    cudaGetSymbolAddress((void**)&xs,   d_xs);
    cudaGetSymbolAddress((void**)&xdbl, d_xdbl);
    cudaGetSymbolAddress((void**)&dt,   d_dt);
    cudaGetSymbolAddress((void**)&y,    d_y);
    cudaGetSymbolAddress((void**)&tmp,  d_tmp);

    // A = -exp(A_log)
    prep_A_kernel<<<(DINNER * DSTATE + 255) / 256, 256>>>(A_log);

    // G1: xz = x @ W_in^T   [4096,1024] x [4096,1024]^T -> [4096,4096]
    gemm_nt<0><<<dim3(2 * DINNER / BN, NROWS / BM), 256>>>(
        x, W_in, nullptr, xz, NROWS, 2 * DINNER, DMODEL, DMODEL, 2 * DINNER);

    // conv + silu -> xs
    conv_silu_kernel<<<(NROWS * DINNER) / 256, 256>>>(conv_w, conv_b);

    // G2: x_dbl = xs @ W_xp^T   [4096,2048] x [96,2048]^T -> [4096,96]
    gemm_nt<0><<<dim3((XDBL_W + BN - 1) / BN, NROWS / BM), 256>>>(
        xs, W_xp, nullptr, xdbl, NROWS, XDBL_W, DINNER, DINNER, XDBL_W);

    // G3: dt = softplus(x_dbl[:, :64] @ W_dt^T + b_dt)  -> [4096,2048]
    gemm_nt<2><<<dim3(DINNER / BN, NROWS / BM), 256>>>(
        xdbl, W_dt, b_dt, dt, NROWS, DINNER, DTRANK, XDBL_W, DINNER);

    // fused scan + D skip + silu(z) gate -> y
    scan_kernel<<<256, 256>>>(Dvec);

    // G4: tmp = y @ W_out_ssm^T  [4096,2048] x [1024,2048]^T -> [4096,1024]
    gemm_nt<0><<<dim3(DMODEL / BN, NROWS / BM), 256>>>(
        y, W_out_ssm, nullptr, tmp, NROWS, DMODEL, DINNER, DINNER, DMODEL);

    // G5: out = tmp @ W_out^T + b_out  -> [4096,1024]
    gemm_nt<1><<<dim3(DMODEL / BN, NROWS / BM), 256>>>(
        tmp, W_out, b_out, out, NROWS, DMODEL, DMODEL, DMODEL, DMODEL);
}

// round 2
// speedup vs baseline: 1.2890x; 1.2890x over previous
#include <cuda_runtime.h>
#include <cuda_bf16.h>
#include <cstdint>

// MambaSSMBlock: B=2, L=2048, d_model=1024, d_inner=2048, d_state=16,
// d_conv=4, dt_rank=64
#define BB      2
#define LL      2048
#define DMODEL  1024
#define DINNER  2048
#define DSTATE  16
#define DTRANK  64
#define NROWS   (BB * LL)              // 4096
#define XDBL_W  (DTRANK + 2 * DSTATE)  // 96

// ---------------- scratch (static device globals; no allocs) ----------------
__device__ float d_xz  [(size_t)NROWS * (2 * DINNER)];
__device__ float d_xs  [(size_t)NROWS * DINNER];
__device__ float d_xdbl[(size_t)NROWS * XDBL_W];
__device__ float d_dt  [(size_t)NROWS * DINNER];
__device__ float d_y   [(size_t)NROWS * DINNER];
__device__ float d_tmp [(size_t)NROWS * DMODEL];
__device__ float d_A   [DINNER * DSTATE];

// ---------------- helpers ----------------
__device__ __forceinline__ float silu_f(float v) {
    return v / (1.f + __expf(-v));
}

__global__ void prep_A_kernel(const float* __restrict__ A_log) {
    int i = blockIdx.x * blockDim.x + threadIdx.x;
    if (i < DINNER * DSTATE) d_A[i] = -expf(A_log[i]);
}

// split a pair of floats into packed bf16x2 hi and lo parts
__device__ __forceinline__ void split2(float x, float y, uint32_t& hi, uint32_t& lo) {
    __nv_bfloat162 h = __floats2bfloat162_rn(x, y);
    float2 hf = __bfloat1622float2(h);
    __nv_bfloat162 l = __floats2bfloat162_rn(x - hf.x, y - hf.y);
    hi = *reinterpret_cast<uint32_t*>(&h);
    lo = *reinterpret_cast<uint32_t*>(&l);
}

__device__ __forceinline__ void mma16(float c[4], const uint32_t a[4], const uint32_t b[2]) {
    asm volatile(
        "mma.sync.aligned.m16n8k16.row.col.f32.bf16.bf16.f32 "
        "{%0,%1,%2,%3},{%4,%5,%6,%7},{%8,%9},{%0,%1,%2,%3};"
        : "+f"(c[0]), "+f"(c[1]), "+f"(c[2]), "+f"(c[3])
        : "r"(a[0]), "r"(a[1]), "r"(a[2]), "r"(a[3]), "r"(b[0]), "r"(b[1]));
}

// --------- tensor-core GEMM: C[M,N] = A[M,K] @ W[N,K]^T, bf16 3-mma split ----
// EPI: 0 none, 1 +bias, 2 softplus(v + bias)
// Block = 256 threads (8 warps). BK=32 (16 bf16-pairs). All dims exact
// multiples (no predication).
template<int BM, int BN, int WARPS_M, int WARPS_N, int EPI>
__global__ void __launch_bounds__(256, 2)
gemm_tc(const float* __restrict__ A, const float* __restrict__ W,
        const float* __restrict__ bias, float* __restrict__ C,
        int K, int lda, int ldc)
{
    constexpr int BMP = BM + 8;   // (BMP % 32) == 8 -> conflict-free frag LDS
    constexpr int BNP = BN + 8;
    constexpr int WM = BM / WARPS_M, WN = BN / WARPS_N;
    constexpr int MT = WM / 16, NT = WN / 8;

    __shared__ uint32_t As_hi[16 * BMP];
    __shared__ uint32_t As_lo[16 * BMP];
    __shared__ uint32_t Bs_hi[16 * BNP];
    __shared__ uint32_t Bs_lo[16 * BNP];

    const int tid  = threadIdx.x;
    const int warp = tid >> 5, lane = tid & 31;
    const int wm = (warp / WARPS_N) * WM;
    const int wn = (warp % WARPS_N) * WN;
    const int lr = lane >> 2, lc = lane & 3;

    float c[MT][NT][4];
#pragma unroll
    for (int i = 0; i < MT; i++)
#pragma unroll
        for (int j = 0; j < NT; j++)
#pragma unroll
            for (int t = 0; t < 4; t++) c[i][j][t] = 0.f;

    const float* Ab = A + (size_t)blockIdx.y * BM * lda;
    const float* Wb = W + (size_t)blockIdx.x * BN * (size_t)K;

    for (int k0 = 0; k0 < K; k0 += 32) {
        // load + split A tile [BM x 32] -> As_{hi,lo}[pair][m]
#pragma unroll
        for (int i = tid; i < BM * 8; i += 256) {
            int r = i >> 3, f4 = i & 7;
            float4 v = *(const float4*)(Ab + (size_t)r * lda + k0 + f4 * 4);
            uint32_t h0, l0, h1, l1;
            split2(v.x, v.y, h0, l0);
            split2(v.z, v.w, h1, l1);
            int p = f4 * 2;
            As_hi[(p + 0) * BMP + r] = h0; As_lo[(p + 0) * BMP + r] = l0;
            As_hi[(p + 1) * BMP + r] = h1; As_lo[(p + 1) * BMP + r] = l1;
        }
        // load + split W tile [BN x 32]
#pragma unroll
        for (int i = tid; i < BN * 8; i += 256) {
            int r = i >> 3, f4 = i & 7;
            float4 v = *(const float4*)(Wb + (size_t)r * K + k0 + f4 * 4);
            uint32_t h0, l0, h1, l1;
            split2(v.x, v.y, h0, l0);
            split2(v.z, v.w, h1, l1);
            int p = f4 * 2;
            Bs_hi[(p + 0) * BNP + r] = h0; Bs_lo[(p + 0) * BNP + r] = l0;
            Bs_hi[(p + 1) * BNP + r] = h1; Bs_lo[(p + 1) * BNP + r] = l1;
        }
        __syncthreads();

#pragma unroll
        for (int ks = 0; ks < 2; ks++) {
            const int kb = ks * 8;
            uint32_t ah[MT][4], al[MT][4], bh[NT][2], bl[NT][2];
#pragma unroll
            for (int mt = 0; mt < MT; mt++) {
                int m = wm + mt * 16 + lr;
                ah[mt][0] = As_hi[(kb + lc) * BMP + m];
                ah[mt][1] = As_hi[(kb + lc) * BMP + m + 8];
                ah[mt][2] = As_hi[(kb + lc + 4) * BMP + m];
                ah[mt][3] = As_hi[(kb + lc + 4) * BMP + m + 8];
                al[mt][0] = As_lo[(kb + lc) * BMP + m];
                al[mt][1] = As_lo[(kb + lc) * BMP + m + 8];
                al[mt][2] = As_lo[(kb + lc + 4) * BMP + m];
                al[mt][3] = As_lo[(kb + lc + 4) * BMP + m + 8];
            }
#pragma unroll
            for (int nt = 0; nt < NT; nt++) {
                int n = wn + nt * 8 + lr;
                bh[nt][0] = Bs_hi[(kb + lc) * BNP + n];
                bh[nt][1] = Bs_hi[(kb + lc + 4) * BNP + n];
                bl[nt][0] = Bs_lo[(kb + lc) * BNP + n];
                bl[nt][1] = Bs_lo[(kb + lc + 4) * BNP + n];
            }
#pragma unroll
            for (int mt = 0; mt < MT; mt++)
#pragma unroll
                for (int nt = 0; nt < NT; nt++) {
                    mma16(c[mt][nt], ah[mt], bh[nt]);
                    mma16(c[mt][nt], ah[mt], bl[nt]);
                    mma16(c[mt][nt], al[mt], bh[nt]);
                }
        }
        __syncthreads();
    }

    // epilogue
#pragma unroll
    for (int mt = 0; mt < MT; mt++) {
#pragma unroll
        for (int nt = 0; nt < NT; nt++) {
            int m0 = blockIdx.y * BM + wm + mt * 16 + lr;
            int n  = blockIdx.x * BN + wn + nt * 8 + 2 * lc;
            float2 bv = make_float2(0.f, 0.f);
            if (EPI >= 1) bv = *(const float2*)(bias + n);
            float v0 = c[mt][nt][0], v1 = c[mt][nt][1];
            float v2 = c[mt][nt][2], v3 = c[mt][nt][3];
            if (EPI >= 1) { v0 += bv.x; v1 += bv.y; v2 += bv.x; v3 += bv.y; }
            if (EPI == 2) {
                v0 = (v0 > 20.f) ? v0 : log1pf(__expf(v0));
                v1 = (v1 > 20.f) ? v1 : log1pf(__expf(v1));
                v2 = (v2 > 20.f) ? v2 : log1pf(__expf(v2));
                v3 = (v3 > 20.f) ? v3 : log1pf(__expf(v3));
            }
            *(float2*)(C + (size_t)m0 * ldc + n)       = make_float2(v0, v1);
            *(float2*)(C + (size_t)(m0 + 8) * ldc + n) = make_float2(v2, v3);
        }
    }
}

// ---------------- causal depthwise conv (k=4) + SiLU ----------------
__global__ void __launch_bounds__(256)
conv_silu_kernel(const float* __restrict__ conv_w, const float* __restrict__ conv_b)
{
    int idx = blockIdx.x * blockDim.x + threadIdx.x;
    int d     = idx & (DINNER - 1);
    int rowid = idx >> 11;
    int l     = rowid & (LL - 1);
    const float* base = d_xz + (size_t)rowid * (2 * DINNER) + d;
    const float4 w = *(const float4*)(conv_w + d * 4);
    float acc = conv_b[d];
    if (l >= 3) acc = fmaf(w.x, base[-3 * (2 * DINNER)], acc);
    if (l >= 2) acc = fmaf(w.y, base[-2 * (2 * DINNER)], acc);
    if (l >= 1) acc = fmaf(w.z, base[-1 * (2 * DINNER)], acc);
    acc = fmaf(w.w, base[0], acc);
    d_xs[(size_t)rowid * DINNER + d] = silu_f(acc);
}

// ---------------- fused selective scan + D skip + gate ----------------
__global__ void __launch_bounds__(256)
scan_kernel(const float* __restrict__ Dvec)
{
    const int s    = threadIdx.x & 15;
    const int cloc = threadIdx.x >> 4;
    const int b    = blockIdx.x >> 7;
    const int d    = ((blockIdx.x & 127) << 4) + cloc;

    const float Aval = d_A[d * DSTATE + s];
    const float Dv   = Dvec[d];

    const float* dt_p = d_dt   + (size_t)b * LL * DINNER + d;
    const float* xs_p = d_xs   + (size_t)b * LL * DINNER + d;
    const float* z_p  = d_xz   + (size_t)b * LL * (2 * DINNER) + DINNER + d;
    const float* bc_p = d_xdbl + (size_t)b * LL * XDBL_W + DTRANK + s;
    float*       y_p  = d_y    + (size_t)b * LL * DINNER + d;

    float h = 0.f;
#pragma unroll 4
    for (int l = 0; l < LL; l++) {
        float dtv = __ldg(dt_p);
        float xv  = __ldg(xs_p);
        float Bv  = __ldg(bc_p);
        float Cv  = __ldg(bc_p + DSTATE);
        float a = __expf(dtv * Aval);
        h = fmaf(h, a, dtv * xv * Bv);
        float p = h * Cv;
        p += __shfl_xor_sync(0xffffffffu, p, 8);
        p += __shfl_xor_sync(0xffffffffu, p, 4);
        p += __shfl_xor_sync(0xffffffffu, p, 2);
        p += __shfl_xor_sync(0xffffffffu, p, 1);
        if (s == 0) {
            float zv = __ldg(z_p);
            y_p[0] = (p + xv * Dv) * silu_f(zv);
        }
        dt_p += DINNER; xs_p += DINNER; z_p += 2 * DINNER;
        bc_p += XDBL_W; y_p += DINNER;
    }
}

// ---------------- launch ----------------
extern "C" void kernel_launch(void* const* d_in, const int* in_sizes, int n_in,
                              void* d_out, int out_size)
{
    const float* x         = (const float*)d_in[0];
    const float* W_in      = (const float*)d_in[1];
    const float* conv_w    = (const float*)d_in[2];
    const float* conv_b    = (const float*)d_in[3];
    const float* W_xp      = (const float*)d_in[4];
    const float* W_dt      = (const float*)d_in[5];
    const float* b_dt      = (const float*)d_in[6];
    const float* A_log     = (const float*)d_in[7];
    const float* Dvec      = (const float*)d_in[8];
    const float* W_out_ssm = (const float*)d_in[9];
    const float* W_out     = (const float*)d_in[10];
    const float* b_out     = (const float*)d_in[11];
    float* out = (float*)d_out;

    float *xz, *xs, *xdbl, *dt, *y, *tmp;
    cudaGetSymbolAddress((void**)&xz,   d_xz);
    cudaGetSymbolAddress((void**)&xs,   d_xs);
    cudaGetSymbolAddress((void**)&xdbl, d_xdbl);
    cudaGetSymbolAddress((void**)&dt,   d_dt);
    cudaGetSymbolAddress((void**)&y,    d_y);
    cudaGetSymbolAddress((void**)&tmp,  d_tmp);

    prep_A_kernel<<<(DINNER * DSTATE + 255) / 256, 256>>>(A_log);

    // G1: xz = x @ W_in^T  [4096,1024]x[4096,1024]^T -> [4096,4096]
    gemm_tc<128, 64, 4, 2, 0><<<dim3(2 * DINNER / 64, NROWS / 128), 256>>>(
        x, W_in, nullptr, xz, DMODEL, DMODEL, 2 * DINNER);

    conv_silu_kernel<<<(NROWS * DINNER) / 256, 256>>>(conv_w, conv_b);

    // G2: x_dbl = xs @ W_xp^T  [4096,2048]x[96,2048]^T -> [4096,96]
    gemm_tc<32, 96, 2, 4, 0><<<dim3(1, NROWS / 32), 256>>>(
        xs, W_xp, nullptr, xdbl, DINNER, DINNER, XDBL_W);

    // G3: dt = softplus(x_dbl[:, :64] @ W_dt^T + b_dt) -> [4096,2048]
    gemm_tc<128, 64, 4, 2, 2><<<dim3(DINNER / 64, NROWS / 128), 256>>>(
        xdbl, W_dt, b_dt, dt, DTRANK, XDBL_W, DINNER);

    // fused scan + D skip + silu(z) gate -> y
    scan_kernel<<<256, 256>>>(Dvec);

    // G4: tmp = y @ W_out_ssm^T  -> [4096,1024]
    gemm_tc<128, 64, 4, 2, 0><<<dim3(DMODEL / 64, NROWS / 128), 256>>>(
        y, W_out_ssm, nullptr, tmp, DINNER, DINNER, DMODEL);

    // G5: out = tmp @ W_out^T + b_out -> [4096,1024]
    gemm_tc<128, 64, 4, 2, 1><<<dim3(DMODEL / 64, NROWS / 128), 256>>>(
        tmp, W_out, b_out, out, DMODEL, DMODEL, DMODEL);
}

// round 3
// speedup vs baseline: 1.7132x; 1.3291x over previous
#include <cuda_runtime.h>
#include <cuda_bf16.h>
#include <cstdint>

// MambaSSMBlock: B=2, L=2048, d_model=1024, d_inner=2048, d_state=16,
// d_conv=4, dt_rank=64
#define BB      2
#define LL      2048
#define DMODEL  1024
#define DINNER  2048
#define DSTATE  16
#define DTRANK  64
#define NROWS   (BB * LL)              // 4096
#define XDBL_W  (DTRANK + 2 * DSTATE)  // 96
#define G2SPL   8                      // split-K chunks for G2

// ---------------- fp32 scratch ----------------
__device__ float d_xz  [(size_t)NROWS * (2 * DINNER)];
__device__ float d_xs  [(size_t)NROWS * DINNER];
__device__ float d_xdbl[(size_t)NROWS * XDBL_W];
__device__ float d_dt  [(size_t)NROWS * DINNER];
__device__ float d_A   [DINNER * DSTATE];
__device__ float d_part[(size_t)G2SPL * NROWS * XDBL_W];

// ---------------- packed bf16 hi/lo scratch (pairs along K) ----------------
__device__ uint32_t d_x_hi  [(size_t)NROWS * (DMODEL / 2)];
__device__ uint32_t d_x_lo  [(size_t)NROWS * (DMODEL / 2)];
__device__ uint32_t d_Win_hi[(size_t)(2 * DINNER) * (DMODEL / 2)];
__device__ uint32_t d_Win_lo[(size_t)(2 * DINNER) * (DMODEL / 2)];
__device__ uint32_t d_Wxp_hi[(size_t)XDBL_W * (DINNER / 2)];
__device__ uint32_t d_Wxp_lo[(size_t)XDBL_W * (DINNER / 2)];
__device__ uint32_t d_Wdt_hi[(size_t)DINNER * (DTRANK / 2)];
__device__ uint32_t d_Wdt_lo[(size_t)DINNER * (DTRANK / 2)];
__device__ uint32_t d_Wos_hi[(size_t)DMODEL * (DINNER / 2)];
__device__ uint32_t d_Wos_lo[(size_t)DMODEL * (DINNER / 2)];
__device__ uint32_t d_Wo_hi [(size_t)DMODEL * (DMODEL / 2)];
__device__ uint32_t d_Wo_lo [(size_t)DMODEL * (DMODEL / 2)];
__device__ uint32_t d_xs_hi [(size_t)NROWS * (DINNER / 2)];
__device__ uint32_t d_xs_lo [(size_t)NROWS * (DINNER / 2)];
__device__ uint32_t d_xd_hi [(size_t)NROWS * (XDBL_W / 2)];
__device__ uint32_t d_xd_lo [(size_t)NROWS * (XDBL_W / 2)];
__device__ uint32_t d_y_hi  [(size_t)NROWS * (DINNER / 2)];
__device__ uint32_t d_y_lo  [(size_t)NROWS * (DINNER / 2)];
__device__ uint32_t d_tmp_hi[(size_t)NROWS * (DMODEL / 2)];
__device__ uint32_t d_tmp_lo[(size_t)NROWS * (DMODEL / 2)];

// ---------------- helpers ----------------
__device__ __forceinline__ float silu_f(float v) {
    return v / (1.f + __expf(-v));
}

__device__ __forceinline__ void split2(float x, float y, uint32_t& hi, uint32_t& lo) {
    __nv_bfloat162 h = __floats2bfloat162_rn(x, y);
    float2 hf = __bfloat1622float2(h);
    __nv_bfloat162 l = __floats2bfloat162_rn(x - hf.x, y - hf.y);
    hi = *reinterpret_cast<uint32_t*>(&h);
    lo = *reinterpret_cast<uint32_t*>(&l);
}

__device__ __forceinline__ void mma16(float c[4], const uint32_t a[4], const uint32_t b[2]) {
    asm volatile(
        "mma.sync.aligned.m16n8k16.row.col.f32.bf16.bf16.f32 "
        "{%0,%1,%2,%3},{%4,%5,%6,%7},{%8,%9},{%0,%1,%2,%3};"
        : "+f"(c[0]), "+f"(c[1]), "+f"(c[2]), "+f"(c[3])
        : "r"(a[0]), "r"(a[1]), "r"(a[2]), "r"(a[3]), "r"(b[0]), "r"(b[1]));
}

__device__ __forceinline__ void ldm_x4(uint32_t r[4], uint32_t addr) {
    asm volatile("ldmatrix.sync.aligned.m8n8.x4.shared.b16 {%0,%1,%2,%3}, [%4];"
                 : "=r"(r[0]), "=r"(r[1]), "=r"(r[2]), "=r"(r[3]) : "r"(addr));
}
__device__ __forceinline__ void ldm_x2(uint32_t r[2], uint32_t addr) {
    asm volatile("ldmatrix.sync.aligned.m8n8.x2.shared.b16 {%0,%1}, [%2];"
                 : "=r"(r[0]), "=r"(r[1]) : "r"(addr));
}
__device__ __forceinline__ void cpa16(uint32_t dst, const void* src) {
    asm volatile("cp.async.cg.shared.global [%0], [%1], 16;" :: "r"(dst), "l"(src));
}
__device__ __forceinline__ void cpa_commit() {
    asm volatile("cp.async.commit_group;");
}
template <int N>
__device__ __forceinline__ void cpa_wait() {
    asm volatile("cp.async.wait_group %0;" :: "n"(N));
}

// ---------------- small kernels ----------------
__global__ void prep_A_kernel(const float* __restrict__ A_log) {
    int i = blockIdx.x * blockDim.x + threadIdx.x;
    if (i < DINNER * DSTATE) d_A[i] = -expf(A_log[i]);
}

__global__ void split_kernel(const float* __restrict__ in, uint32_t* __restrict__ hi,
                             uint32_t* __restrict__ lo, int npairs) {
    int i = blockIdx.x * blockDim.x + threadIdx.x;
    if (i < npairs) {
        float2 v = reinterpret_cast<const float2*>(in)[i];
        split2(v.x, v.y, hi[i], lo[i]);
    }
}

// ============ bf16 split tensor-core GEMM with cp.async + ldmatrix ==========
// C[M,N] = A[M,K] @ W[N,K]^T, where A/W supplied as packed bf16 hi/lo pairs.
// EPI: 0 fp32, 1 fp32+bias, 2 softplus(v+bias), 3 write packed hi/lo.
// 256 threads, 8 warps (WARPS_M x WARPS_N), BK=16 (8 pairs), 2-stage pipeline.
template<int BM, int BN, int WARPS_M, int WARPS_N, int EPI>
__global__ void __launch_bounds__(256, 2)
gemm_bf(const uint32_t* __restrict__ Ah, const uint32_t* __restrict__ Al,
        const uint32_t* __restrict__ Bh, const uint32_t* __restrict__ Bl,
        const float* __restrict__ bias, float* __restrict__ C,
        uint32_t* __restrict__ Chi, uint32_t* __restrict__ Clo,
        int kpairs, int lda, int ldb, int ldc, int c_chunk_stride)
{
    constexpr int P = 12;                        // smem row pitch (words), 8 data + 4 pad
    constexpr int STAGE = (2 * BM + 2 * BN) * P; // words per stage
    constexpr int WM = BM / WARPS_M, WN = BN / WARPS_N;
    constexpr int MT = WM / 16, NT = WN / 8;

    __shared__ __align__(16) uint32_t sm[2 * STAGE];
    const uint32_t smu = (uint32_t)__cvta_generic_to_shared(sm);

    const int tid = threadIdx.x;
    const int warp = tid >> 5, lane = tid & 31;
    const int wm = (warp / WARPS_N) * WM;
    const int wn = (warp % WARPS_N) * WN;

    float c[MT][NT][4];
#pragma unroll
    for (int i = 0; i < MT; i++)
#pragma unroll
        for (int j = 0; j < NT; j++)
#pragma unroll
            for (int t = 0; t < 4; t++) c[i][j][t] = 0.f;

    const size_t arow0 = (size_t)blockIdx.y * BM;
    const size_t brow0 = (size_t)blockIdx.x * BN;
    const int kp_base = blockIdx.z * kpairs;
    if (EPI == 0 && c_chunk_stride) C += (size_t)blockIdx.z * c_chunk_stride;

    auto load_stage = [&](int s, int kp) {
        uint32_t base = smu + s * STAGE * 4;
#pragma unroll 1
        for (int i = tid; i < BM * 2; i += 256) {
            int r = i >> 1, cg = (i & 1) * 4;
            size_t go = (arow0 + r) * (size_t)lda + kp + cg;
            cpa16(base + (r * P + cg) * 4, Ah + go);
            cpa16(base + (BM * P + r * P + cg) * 4, Al + go);
        }
#pragma unroll 1
        for (int i = tid; i < BN * 2; i += 256) {
            int r = i >> 1, cg = (i & 1) * 4;
            size_t go = (brow0 + r) * (size_t)ldb + kp + cg;
            cpa16(base + (2 * BM * P + r * P + cg) * 4, Bh + go);
            cpa16(base + ((2 * BM + BN) * P + r * P + cg) * 4, Bl + go);
        }
    };

    const int nk = kpairs / 8;
    load_stage(0, kp_base);
    cpa_commit();

    const int la = lane & 15, lg = lane >> 4;
    const int lb = lane & 7, lbg = (lane >> 3) & 1;

    for (int kt = 0; kt < nk; kt++) {
        if (kt + 1 < nk) { load_stage((kt + 1) & 1, kp_base + (kt + 1) * 8); cpa_commit(); }
        if (kt + 1 < nk) cpa_wait<1>(); else cpa_wait<0>();
        __syncthreads();

        const uint32_t aHi = smu + ((kt & 1) * STAGE) * 4;
        const uint32_t aLo = aHi + BM * P * 4;
        const uint32_t bHi = aHi + 2 * BM * P * 4;
        const uint32_t bLo = bHi + BN * P * 4;

        uint32_t ah[MT][4], al[MT][4], bh[NT][2], bl[NT][2];
#pragma unroll
        for (int mt = 0; mt < MT; mt++) {
            uint32_t off = ((wm + mt * 16 + la) * P + lg * 4) * 4;
            ldm_x4(ah[mt], aHi + off);
            ldm_x4(al[mt], aLo + off);
        }
#pragma unroll
        for (int nt = 0; nt < NT; nt++) {
            uint32_t off = ((wn + nt * 8 + lb) * P + lbg * 4) * 4;
            ldm_x2(bh[nt], bHi + off);
            ldm_x2(bl[nt], bLo + off);
        }
#pragma unroll
        for (int mt = 0; mt < MT; mt++)
#pragma unroll
            for (int nt = 0; nt < NT; nt++) {
                mma16(c[mt][nt], ah[mt], bh[nt]);
                mma16(c[mt][nt], ah[mt], bl[nt]);
                mma16(c[mt][nt], al[mt], bh[nt]);
            }
        __syncthreads();
    }

    // ---------------- epilogue ----------------
#pragma unroll
    for (int mt = 0; mt < MT; mt++) {
#pragma unroll
        for (int nt = 0; nt < NT; nt++) {
            int m0 = blockIdx.y * BM + wm + mt * 16 + (lane >> 2);
            int n  = blockIdx.x * BN + wn + nt * 8 + 2 * (lane & 3);
            float v0 = c[mt][nt][0], v1 = c[mt][nt][1];
            float v2 = c[mt][nt][2], v3 = c[mt][nt][3];
            if (EPI == 1 || EPI == 2) {
                float2 bv = *(const float2*)(bias + n);
                v0 += bv.x; v1 += bv.y; v2 += bv.x; v3 += bv.y;
            }
            if (EPI == 2) {
                v0 = (v0 > 20.f) ? v0 : log1pf(__expf(v0));
                v1 = (v1 > 20.f) ? v1 : log1pf(__expf(v1));
                v2 = (v2 > 20.f) ? v2 : log1pf(__expf(v2));
                v3 = (v3 > 20.f) ? v3 : log1pf(__expf(v3));
            }
            if (EPI <= 2) {
                *(float2*)(C + (size_t)m0 * ldc + n)       = make_float2(v0, v1);
                *(float2*)(C + (size_t)(m0 + 8) * ldc + n) = make_float2(v2, v3);
            } else {
                uint32_t h, l;
                split2(v0, v1, h, l);
                Chi[(size_t)m0 * ldc + (n >> 1)] = h;
                Clo[(size_t)m0 * ldc + (n >> 1)] = l;
                split2(v2, v3, h, l);
                Chi[(size_t)(m0 + 8) * ldc + (n >> 1)] = h;
                Clo[(size_t)(m0 + 8) * ldc + (n >> 1)] = l;
            }
        }
    }
}

// ---------------- G2 split-K reduce: partials -> xdbl fp32 + hi/lo ----------
__global__ void g2_reduce_kernel() {
    int i = blockIdx.x * blockDim.x + threadIdx.x;   // pairs over [4096 x 96]
    if (i < NROWS * XDBL_W / 2) {
        float s0 = 0.f, s1 = 0.f;
#pragma unroll
        for (int z = 0; z < G2SPL; z++) {
            float2 v = reinterpret_cast<const float2*>(d_part + (size_t)z * NROWS * XDBL_W)[i];
            s0 += v.x; s1 += v.y;
        }
        reinterpret_cast<float2*>(d_xdbl)[i] = make_float2(s0, s1);
        split2(s0, s1, d_xd_hi[i], d_xd_lo[i]);
    }
}

// ---------------- causal depthwise conv (k=4) + SiLU, writes fp32 + hi/lo ---
__global__ void __launch_bounds__(256)
conv_silu_kernel(const float* __restrict__ conv_w, const float* __restrict__ conv_b)
{
    int idx = blockIdx.x * blockDim.x + threadIdx.x;
    int d     = idx & (DINNER - 1);
    int rowid = idx >> 11;
    int l     = rowid & (LL - 1);
    const float* base = d_xz + (size_t)rowid * (2 * DINNER) + d;
    const float4 w = *(const float4*)(conv_w + d * 4);
    float acc = conv_b[d];
    if (l >= 3) acc = fmaf(w.x, base[-3 * (2 * DINNER)], acc);
    if (l >= 2) acc = fmaf(w.y, base[-2 * (2 * DINNER)], acc);
    if (l >= 1) acc = fmaf(w.z, base[-1 * (2 * DINNER)], acc);
    acc = fmaf(w.w, base[0], acc);
    float r = silu_f(acc);
    d_xs[(size_t)rowid * DINNER + d] = r;
    float rn = __shfl_xor_sync(0xffffffffu, r, 1);
    if ((d & 1) == 0) {
        uint32_t h, lo;
        split2(r, rn, h, lo);
        size_t o = (size_t)rowid * (DINNER / 2) + (d >> 1);
        d_xs_hi[o] = h; d_xs_lo[o] = lo;
    }
}

// ---------------- fused selective scan + D skip + gate, writes y hi/lo ------
__global__ void __launch_bounds__(256)
scan_kernel(const float* __restrict__ Dvec)
{
    const int lane = threadIdx.x & 31;
    const int s    = threadIdx.x & 15;
    const int cloc = threadIdx.x >> 4;
    const int b    = blockIdx.x >> 7;
    const int d    = ((blockIdx.x & 127) << 4) + cloc;

    const float Aval = d_A[d * DSTATE + s];
    const float Dv   = Dvec[d];

    const float* dt_p = d_dt   + (size_t)b * LL * DINNER + d;
    const float* xs_p = d_xs   + (size_t)b * LL * DINNER + d;
    const float* z_p  = d_xz   + (size_t)b * LL * (2 * DINNER) + DINNER + d;
    const float* bc_p = d_xdbl + (size_t)b * LL * XDBL_W + DTRANK + s;
    size_t yo = (size_t)b * LL * (DINNER / 2) + (d >> 1);

    float h = 0.f;
#pragma unroll 4
    for (int l = 0; l < LL; l++) {
        float dtv = __ldg(dt_p);
        float xv  = __ldg(xs_p);
        float Bv  = __ldg(bc_p);
        float Cv  = __ldg(bc_p + DSTATE);
        float zv  = __ldg(z_p);
        float a = __expf(dtv * Aval);
        h = fmaf(h, a, dtv * xv * Bv);
        float p = h * Cv;
        p += __shfl_xor_sync(0xffffffffu, p, 8);
        p += __shfl_xor_sync(0xffffffffu, p, 4);
        p += __shfl_xor_sync(0xffffffffu, p, 2);
        p += __shfl_xor_sync(0xffffffffu, p, 1);
        float yv = (p + xv * Dv) * silu_f(zv);
        float yO = __shfl_sync(0xffffffffu, yv, 16);
        if (lane == 0) {
            uint32_t hh, ll;
            split2(yv, yO, hh, ll);
            d_y_hi[yo] = hh; d_y_lo[yo] = ll;
        }
        dt_p += DINNER; xs_p += DINNER; z_p += 2 * DINNER;
        bc_p += XDBL_W; yo += DINNER / 2;
    }
}

// ---------------- launch ----------------
extern "C" void kernel_launch(void* const* d_in, const int* in_sizes, int n_in,
                              void* d_out, int out_size)
{
    const float* x         = (const float*)d_in[0];
    const float* W_in      = (const float*)d_in[1];
    const float* conv_w    = (const float*)d_in[2];
    const float* conv_b    = (const float*)d_in[3];
    const float* W_xp      = (const float*)d_in[4];
    const float* W_dt      = (const float*)d_in[5];
    const float* b_dt      = (const float*)d_in[6];
    const float* A_log     = (const float*)d_in[7];
    const float* Dvec      = (const float*)d_in[8];
    const float* W_out_ssm = (const float*)d_in[9];
    const float* W_out     = (const float*)d_in[10];
    const float* b_out     = (const float*)d_in[11];
    float* out = (float*)d_out;

    float *xz, *xdbl, *dt;
    cudaGetSymbolAddress((void**)&xz,   d_xz);
    cudaGetSymbolAddress((void**)&xdbl, d_xdbl);
    cudaGetSymbolAddress((void**)&dt,   d_dt);
    float* part; cudaGetSymbolAddress((void**)&part, d_part);

    uint32_t *x_hi, *x_lo, *Win_hi, *Win_lo, *Wxp_hi, *Wxp_lo, *Wdt_hi, *Wdt_lo;
    uint32_t *Wos_hi, *Wos_lo, *Wo_hi, *Wo_lo, *xs_hi, *xs_lo, *xd_hi, *xd_lo;
    uint32_t *y_hi, *y_lo, *tmp_hi, *tmp_lo;
    cudaGetSymbolAddress((void**)&x_hi,   d_x_hi);   cudaGetSymbolAddress((void**)&x_lo,   d_x_lo);
    cudaGetSymbolAddress((void**)&Win_hi, d_Win_hi); cudaGetSymbolAddress((void**)&Win_lo, d_Win_lo);
    cudaGetSymbolAddress((void**)&Wxp_hi, d_Wxp_hi); cudaGetSymbolAddress((void**)&Wxp_lo, d_Wxp_lo);
    cudaGetSymbolAddress((void**)&Wdt_hi, d_Wdt_hi); cudaGetSymbolAddress((void**)&Wdt_lo, d_Wdt_lo);
    cudaGetSymbolAddress((void**)&Wos_hi, d_Wos_hi); cudaGetSymbolAddress((void**)&Wos_lo, d_Wos_lo);
    cudaGetSymbolAddress((void**)&Wo_hi,  d_Wo_hi);  cudaGetSymbolAddress((void**)&Wo_lo,  d_Wo_lo);
    cudaGetSymbolAddress((void**)&xs_hi,  d_xs_hi);  cudaGetSymbolAddress((void**)&xs_lo,  d_xs_lo);
    cudaGetSymbolAddress((void**)&xd_hi,  d_xd_hi);  cudaGetSymbolAddress((void**)&xd_lo,  d_xd_lo);
    cudaGetSymbolAddress((void**)&y_hi,   d_y_hi);   cudaGetSymbolAddress((void**)&y_lo,   d_y_lo);
    cudaGetSymbolAddress((void**)&tmp_hi, d_tmp_hi); cudaGetSymbolAddress((void**)&tmp_lo, d_tmp_lo);

    prep_A_kernel<<<(DINNER * DSTATE + 255) / 256, 256>>>(A_log);

    // splits (weights + x)
    auto npb = [](int n) { return (n + 255) / 256; };
    split_kernel<<<npb(NROWS * DMODEL / 2), 256>>>(x, x_hi, x_lo, NROWS * DMODEL / 2);
    split_kernel<<<npb(2 * DINNER * DMODEL / 2), 256>>>(W_in, Win_hi, Win_lo, 2 * DINNER * DMODEL / 2);
    split_kernel<<<npb(XDBL_W * DINNER / 2), 256>>>(W_xp, Wxp_hi, Wxp_lo, XDBL_W * DINNER / 2);
    split_kernel<<<npb(DINNER * DTRANK / 2), 256>>>(W_dt, Wdt_hi, Wdt_lo, DINNER * DTRANK / 2);
    split_kernel<<<npb(DMODEL * DINNER / 2), 256>>>(W_out_ssm, Wos_hi, Wos_lo, DMODEL * DINNER / 2);
    split_kernel<<<npb(DMODEL * DMODEL / 2), 256>>>(W_out, Wo_hi, Wo_lo, DMODEL * DMODEL / 2);

    // G1: xz = x @ W_in^T  -> [4096,4096] fp32
    gemm_bf<128, 64, 2, 4, 0><<<dim3(2 * DINNER / 64, NROWS / 128, 1), 256>>>(
        x_hi, x_lo, Win_hi, Win_lo, nullptr, xz, nullptr, nullptr,
        DMODEL / 2, DMODEL / 2, DMODEL / 2, 2 * DINNER, 0);

    conv_silu_kernel<<<(NROWS * DINNER) / 256, 256>>>(conv_w, conv_b);

    // G2 split-K: partials[z] = xs @ W_xp^T (chunk z), then reduce
    gemm_bf<128, 96, 2, 4, 0><<<dim3(1, NROWS / 128, G2SPL), 256>>>(
        xs_hi, xs_lo, Wxp_hi, Wxp_lo, nullptr, part, nullptr, nullptr,
        (DINNER / 2) / G2SPL, DINNER / 2, DINNER / 2, XDBL_W, NROWS * XDBL_W);
    g2_reduce_kernel<<<npb(NROWS * XDBL_W / 2), 256>>>();

    // G3: dt = softplus(xdbl[:, :64] @ W_dt^T + b_dt) -> [4096,2048] fp32
    gemm_bf<128, 64, 2, 4, 2><<<dim3(DINNER / 64, NROWS / 128, 1), 256>>>(
        xd_hi, xd_lo, Wdt_hi, Wdt_lo, b_dt, dt, nullptr, nullptr,
        DTRANK / 2, XDBL_W / 2, DTRANK / 2, DINNER, 0);

    // fused scan + D skip + silu(z) gate -> y hi/lo
    scan_kernel<<<256, 256>>>(Dvec);

    // G4: tmp = y @ W_out_ssm^T -> hi/lo packed [4096,512]
    gemm_bf<128, 64, 2, 4, 3><<<dim3(DMODEL / 64, NROWS / 128, 1), 256>>>(
        y_hi, y_lo, Wos_hi, Wos_lo, nullptr, nullptr, tmp_hi, tmp_lo,
        DINNER / 2, DINNER / 2, DINNER / 2, DMODEL / 2, 0);

    // G5: out = tmp @ W_out^T + b_out -> [4096,1024] fp32
    gemm_bf<128, 64, 2, 4, 1><<<dim3(DMODEL / 64, NROWS / 128, 1), 256>>>(
        tmp_hi, tmp_lo, Wo_hi, Wo_lo, b_out, out, nullptr, nullptr,
        DMODEL / 2, DMODEL / 2, DMODEL / 2, DMODEL, 0);
}

// round 5
// speedup vs baseline: 3.1111x; 1.8160x over previous
#include <cuda_runtime.h>
#include <cuda_bf16.h>
#include <cstdint>

// MambaSSMBlock: B=2, L=2048, d_model=1024, d_inner=2048, d_state=16,
// d_conv=4, dt_rank=64
#define BB      2
#define LL      2048
#define DMODEL  1024
#define DINNER  2048
#define DSTATE  16
#define DTRANK  64
#define NROWS   (BB * LL)              // 4096
#define XDBL_W  (DTRANK + 2 * DSTATE)  // 96
#define G2SPL   8                      // split-K chunks for G2
#define NC      16                     // scan chunks along L
#define CL      (LL / NC)              // 128 steps per chunk
#define NGID    (BB * DINNER * DSTATE) // 65536 scan lanes

// ---------------- fp32 scratch ----------------
__device__ float d_xz  [(size_t)NROWS * (2 * DINNER)];
__device__ float d_xs  [(size_t)NROWS * DINNER];
__device__ float d_xdbl[(size_t)NROWS * XDBL_W];
__device__ float d_dt  [(size_t)NROWS * DINNER];
__device__ float d_A   [DINNER * DSTATE];
__device__ float d_part[(size_t)G2SPL * NROWS * XDBL_W];
__device__ float d_Pc  [(size_t)NC * NGID];
__device__ float d_Qc  [(size_t)NC * NGID];
__device__ float d_hin [(size_t)NC * NGID];

// ---------------- packed bf16 hi/lo scratch (pairs along K) ----------------
__device__ uint32_t d_x_hi  [(size_t)NROWS * (DMODEL / 2)];
__device__ uint32_t d_x_lo  [(size_t)NROWS * (DMODEL / 2)];
__device__ uint32_t d_Win_hi[(size_t)(2 * DINNER) * (DMODEL / 2)];
__device__ uint32_t d_Win_lo[(size_t)(2 * DINNER) * (DMODEL / 2)];
__device__ uint32_t d_Wxp_hi[(size_t)XDBL_W * (DINNER / 2)];
__device__ uint32_t d_Wxp_lo[(size_t)XDBL_W * (DINNER / 2)];
__device__ uint32_t d_Wdt_hi[(size_t)DINNER * (DTRANK / 2)];
__device__ uint32_t d_Wdt_lo[(size_t)DINNER * (DTRANK / 2)];
__device__ uint32_t d_Wos_hi[(size_t)DMODEL * (DINNER / 2)];
__device__ uint32_t d_Wos_lo[(size_t)DMODEL * (DINNER / 2)];
__device__ uint32_t d_Wo_hi [(size_t)DMODEL * (DMODEL / 2)];
__device__ uint32_t d_Wo_lo [(size_t)DMODEL * (DMODEL / 2)];
__device__ uint32_t d_xs_hi [(size_t)NROWS * (DINNER / 2)];
__device__ uint32_t d_xs_lo [(size_t)NROWS * (DINNER / 2)];
__device__ uint32_t d_xd_hi [(size_t)NROWS * (XDBL_W / 2)];
__device__ uint32_t d_xd_lo [(size_t)NROWS * (XDBL_W / 2)];
__device__ uint32_t d_y_hi  [(size_t)NROWS * (DINNER / 2)];
__device__ uint32_t d_y_lo  [(size_t)NROWS * (DINNER / 2)];
__device__ uint32_t d_tmp_hi[(size_t)NROWS * (DMODEL / 2)];
__device__ uint32_t d_tmp_lo[(size_t)NROWS * (DMODEL / 2)];

// ---------------- helpers ----------------
__device__ __forceinline__ float silu_f(float v) {
    return v / (1.f + __expf(-v));
}

__device__ __forceinline__ void split2(float x, float y, uint32_t& hi, uint32_t& lo) {
    __nv_bfloat162 h = __floats2bfloat162_rn(x, y);
    float2 hf = __bfloat1622float2(h);
    __nv_bfloat162 l = __floats2bfloat162_rn(x - hf.x, y - hf.y);
    hi = *reinterpret_cast<uint32_t*>(&h);
    lo = *reinterpret_cast<uint32_t*>(&l);
}

__device__ __forceinline__ void mma16(float c[4], const uint32_t a[4], const uint32_t b[2]) {
    asm volatile(
        "mma.sync.aligned.m16n8k16.row.col.f32.bf16.bf16.f32 "
        "{%0,%1,%2,%3},{%4,%5,%6,%7},{%8,%9},{%0,%1,%2,%3};"
        : "+f"(c[0]), "+f"(c[1]), "+f"(c[2]), "+f"(c[3])
        : "r"(a[0]), "r"(a[1]), "r"(a[2]), "r"(a[3]), "r"(b[0]), "r"(b[1]));
}

__device__ __forceinline__ void ldm_x4(uint32_t r[4], uint32_t addr) {
    asm volatile("ldmatrix.sync.aligned.m8n8.x4.shared.b16 {%0,%1,%2,%3}, [%4];"
                 : "=r"(r[0]), "=r"(r[1]), "=r"(r[2]), "=r"(r[3]) : "r"(addr));
}
__device__ __forceinline__ void ldm_x2(uint32_t r[2], uint32_t addr) {
    asm volatile("ldmatrix.sync.aligned.m8n8.x2.shared.b16 {%0,%1}, [%2];"
                 : "=r"(r[0]), "=r"(r[1]) : "r"(addr));
}
__device__ __forceinline__ void cpa16(uint32_t dst, const void* src) {
    asm volatile("cp.async.cg.shared.global [%0], [%1], 16;" :: "r"(dst), "l"(src));
}
__device__ __forceinline__ void cpa_commit() {
    asm volatile("cp.async.commit_group;");
}
template <int N>
__device__ __forceinline__ void cpa_wait() {
    asm volatile("cp.async.wait_group %0;" :: "n"(N));
}

// ---------------- small kernels ----------------
__global__ void prep_A_kernel(const float* __restrict__ A_log) {
    int i = blockIdx.x * blockDim.x + threadIdx.x;
    if (i < DINNER * DSTATE) d_A[i] = -expf(A_log[i]);
}

// fused split of all six fp32->bf16(hi/lo) conversions; compile-time segments
#define SP0 (NROWS * DMODEL / 2)            // x       2097152
#define SP1 (2 * DINNER * DMODEL / 2)       // W_in    4194304
#define SP2 (XDBL_W * DINNER / 2)           // W_xp      98304
#define SP3 (DINNER * DTRANK / 2)           // W_dt      65536
#define SP4 (DMODEL * DINNER / 2)           // W_out_ssm 1048576
#define SP5 (DMODEL * DMODEL / 2)           // W_out     524288
#define SPTOT (SP0 + SP1 + SP2 + SP3 + SP4 + SP5)

__global__ void __launch_bounds__(256)
split_all_kernel(const float* __restrict__ x, const float* __restrict__ Win,
                 const float* __restrict__ Wxp, const float* __restrict__ Wdt,
                 const float* __restrict__ Wos, const float* __restrict__ Wo)
{
    int i = blockIdx.x * blockDim.x + threadIdx.x;
    if (i >= SPTOT) return;
    const float* src; uint32_t *hi, *lo; int off;
    if (i < SP0)                       { src = x;   hi = d_x_hi;   lo = d_x_lo;   off = i; }
    else if (i < SP0+SP1)              { src = Win; hi = d_Win_hi; lo = d_Win_lo; off = i - SP0; }
    else if (i < SP0+SP1+SP2)          { src = Wxp; hi = d_Wxp_hi; lo = d_Wxp_lo; off = i - (SP0+SP1); }
    else if (i < SP0+SP1+SP2+SP3)      { src = Wdt; hi = d_Wdt_hi; lo = d_Wdt_lo; off = i - (SP0+SP1+SP2); }
    else if (i < SP0+SP1+SP2+SP3+SP4)  { src = Wos; hi = d_Wos_hi; lo = d_Wos_lo; off = i - (SP0+SP1+SP2+SP3); }
    else                               { src = Wo;  hi = d_Wo_hi;  lo = d_Wo_lo;  off = i - (SP0+SP1+SP2+SP3+SP4); }
    float2 v = reinterpret_cast<const float2*>(src)[off];
    split2(v.x, v.y, hi[off], lo[off]);
}

// ============ bf16 split tensor-core GEMM, 3-stage cp.async, 1 sync/iter ====
// C[M,N] = A[M,K] @ W[N,K]^T, packed bf16 hi/lo inputs. DYNAMIC smem (3 stages).
// EPI: 0 fp32, 1 fp32+bias, 2 softplus(v+bias), 3 write packed hi/lo.
template<int BM, int BN, int EPI>
__global__ void __launch_bounds__(256, 1)
gemm_bf(const uint32_t* __restrict__ Ah, const uint32_t* __restrict__ Al,
        const uint32_t* __restrict__ Bh, const uint32_t* __restrict__ Bl,
        const float* __restrict__ bias, float* __restrict__ C,
        uint32_t* __restrict__ Chi, uint32_t* __restrict__ Clo,
        int kpairs, int lda, int ldb, int ldc, int c_chunk_stride)
{
    constexpr int P = 12;                        // smem pitch (words): 8 data + 4 pad
    constexpr int STAGE = (2 * BM + 2 * BN) * P; // words per stage
    constexpr int WARPS_N = 4;
    constexpr int WM = BM / 2, WN = BN / WARPS_N;
    constexpr int MT = WM / 16, NT = WN / 8;

    extern __shared__ __align__(16) uint32_t sm[];
    const uint32_t smu = (uint32_t)__cvta_generic_to_shared(sm);

    const int tid = threadIdx.x;
    const int warp = tid >> 5, lane = tid & 31;
    const int wm = (warp / WARPS_N) * WM;
    const int wn = (warp % WARPS_N) * WN;

    float c[MT][NT][4];
#pragma unroll
    for (int i = 0; i < MT; i++)
#pragma unroll
        for (int j = 0; j < NT; j++)
#pragma unroll
            for (int t = 0; t < 4; t++) c[i][j][t] = 0.f;

    const size_t arow0 = (size_t)blockIdx.y * BM;
    const size_t brow0 = (size_t)blockIdx.x * BN;
    const int kp_base = blockIdx.z * kpairs;
    if (EPI == 0 && c_chunk_stride) C += (size_t)blockIdx.z * c_chunk_stride;

    auto load_stage = [&](int s, int kp) {
        uint32_t base = smu + s * STAGE * 4;
#pragma unroll 1
        for (int i = tid; i < BM * 2; i += 256) {
            int r = i >> 1, cg = (i & 1) * 4;
            size_t go = (arow0 + r) * (size_t)lda + kp + cg;
            cpa16(base + (r * P + cg) * 4, Ah + go);
            cpa16(base + (BM * P + r * P + cg) * 4, Al + go);
        }
#pragma unroll 1
        for (int i = tid; i < BN * 2; i += 256) {
            int r = i >> 1, cg = (i & 1) * 4;
            size_t go = (brow0 + r) * (size_t)ldb + kp + cg;
            cpa16(base + (2 * BM * P + r * P + cg) * 4, Bh + go);
            cpa16(base + ((2 * BM + BN) * P + r * P + cg) * 4, Bl + go);
        }
    };

    const int nk = kpairs / 8;                   // K/16 iterations
    load_stage(0, kp_base);            cpa_commit();
    load_stage(1 % 3, kp_base + 8);    cpa_commit();

    const int la = lane & 15, lg = lane >> 4;
    const int lb = lane & 7, lbg = (lane >> 3) & 1;

    for (int kt = 0; kt < nk; kt++) {
        if (kt + 2 < nk) cpa_wait<1>(); else cpa_wait<0>();
        __syncthreads();

        const int st = kt % 3;
        const uint32_t aHi = smu + (st * STAGE) * 4;
        const uint32_t aLo = aHi + BM * P * 4;
        const uint32_t bHi = aHi + 2 * BM * P * 4;
        const uint32_t bLo = bHi + BN * P * 4;

        uint32_t ah[MT][4], al[MT][4], bh[NT][2], bl[NT][2];
#pragma unroll
        for (int mt = 0; mt < MT; mt++) {
            uint32_t off = ((wm + mt * 16 + la) * P + lg * 4) * 4;
            ldm_x4(ah[mt], aHi + off);
            ldm_x4(al[mt], aLo + off);
        }
#pragma unroll
        for (int nt = 0; nt < NT; nt++) {
            uint32_t off = ((wn + nt * 8 + lb) * P + lbg * 4) * 4;
            ldm_x2(bh[nt], bHi + off);
            ldm_x2(bl[nt], bLo + off);
        }
#pragma unroll
        for (int mt = 0; mt < MT; mt++)
#pragma unroll
            for (int nt = 0; nt < NT; nt++) {
                mma16(c[mt][nt], ah[mt], bh[nt]);
                mma16(c[mt][nt], ah[mt], bl[nt]);
                mma16(c[mt][nt], al[mt], bh[nt]);
            }

        if (kt + 2 < nk) { load_stage((kt + 2) % 3, kp_base + (kt + 2) * 8); cpa_commit(); }
    }

    // ---------------- epilogue ----------------
#pragma unroll
    for (int mt = 0; mt < MT; mt++) {
#pragma unroll
        for (int nt = 0; nt < NT; nt++) {
            int m0 = blockIdx.y * BM + wm + mt * 16 + (lane >> 2);
            int n  = blockIdx.x * BN + wn + nt * 8 + 2 * (lane & 3);
            float v0 = c[mt][nt][0], v1 = c[mt][nt][1];
            float v2 = c[mt][nt][2], v3 = c[mt][nt][3];
            if (EPI == 1 || EPI == 2) {
                float2 bv = *(const float2*)(bias + n);
                v0 += bv.x; v1 += bv.y; v2 += bv.x; v3 += bv.y;
            }
            if (EPI == 2) {
                v0 = (v0 > 20.f) ? v0 : log1pf(__expf(v0));
                v1 = (v1 > 20.f) ? v1 : log1pf(__expf(v1));
                v2 = (v2 > 20.f) ? v2 : log1pf(__expf(v2));
                v3 = (v3 > 20.f) ? v3 : log1pf(__expf(v3));
            }
            if (EPI <= 2) {
                *(float2*)(C + (size_t)m0 * ldc + n)       = make_float2(v0, v1);
                *(float2*)(C + (size_t)(m0 + 8) * ldc + n) = make_float2(v2, v3);
            } else {
                uint32_t h, l;
                split2(v0, v1, h, l);
                Chi[(size_t)m0 * ldc + (n >> 1)] = h;
                Clo[(size_t)m0 * ldc + (n >> 1)] = l;
                split2(v2, v3, h, l);
                Chi[(size_t)(m0 + 8) * ldc + (n >> 1)] = h;
                Clo[(size_t)(m0 + 8) * ldc + (n >> 1)] = l;
            }
        }
    }
}

// ---------------- G2 split-K reduce ----------------
__global__ void g2_reduce_kernel() {
    int i = blockIdx.x * blockDim.x + threadIdx.x;
    if (i < NROWS * XDBL_W / 2) {
        float s0 = 0.f, s1 = 0.f;
#pragma unroll
        for (int z = 0; z < G2SPL; z++) {
            float2 v = reinterpret_cast<const float2*>(d_part + (size_t)z * NROWS * XDBL_W)[i];
            s0 += v.x; s1 += v.y;
        }
        reinterpret_cast<float2*>(d_xdbl)[i] = make_float2(s0, s1);
        split2(s0, s1, d_xd_hi[i], d_xd_lo[i]);
    }
}

// ---------------- causal depthwise conv (k=4) + SiLU ----------------
__global__ void __launch_bounds__(256)
conv_silu_kernel(const float* __restrict__ conv_w, const float* __restrict__ conv_b)
{
    int idx = blockIdx.x * blockDim.x + threadIdx.x;
    int d     = idx & (DINNER - 1);
    int rowid = idx >> 11;
    int l     = rowid & (LL - 1);
    const float* base = d_xz + (size_t)rowid * (2 * DINNER) + d;
    const float4 w = *(const float4*)(conv_w + d * 4);
    float acc = conv_b[d];
    if (l >= 3) acc = fmaf(w.x, base[-3 * (2 * DINNER)], acc);
    if (l >= 2) acc = fmaf(w.y, base[-2 * (2 * DINNER)], acc);
    if (l >= 1) acc = fmaf(w.z, base[-1 * (2 * DINNER)], acc);
    acc = fmaf(w.w, base[0], acc);
    float r = silu_f(acc);
    d_xs[(size_t)rowid * DINNER + d] = r;
    float rn = __shfl_xor_sync(0xffffffffu, r, 1);
    if ((d & 1) == 0) {
        uint32_t h, lo;
        split2(r, rn, h, lo);
        size_t o = (size_t)rowid * (DINNER / 2) + (d >> 1);
        d_xs_hi[o] = h; d_xs_lo[o] = lo;
    }
}

// ---------------- chunked selective scan ----------------
// phase 1: per (b,d,s,chunk) compute transition h_out = P*h_in + Q
__global__ void __launch_bounds__(256)
scan_phase1_kernel()
{
    const int s    = threadIdx.x & 15;
    const int cloc = threadIdx.x >> 4;
    const int b    = blockIdx.x >> 7;
    const int d    = ((blockIdx.x & 127) << 4) + cloc;
    const int ch   = blockIdx.y;
    const int l0   = ch * CL;

    const float Aval = d_A[d * DSTATE + s];
    const float* dt_p = d_dt   + ((size_t)b * LL + l0) * DINNER + d;
    const float* xs_p = d_xs   + ((size_t)b * LL + l0) * DINNER + d;
    const float* bc_p = d_xdbl + ((size_t)b * LL + l0) * XDBL_W + DTRANK + s;

    float p = 1.f, q = 0.f;
#pragma unroll 4
    for (int t = 0; t < CL; t++) {
        float dtv = __ldg(dt_p);
        float xv  = __ldg(xs_p);
        float Bv  = __ldg(bc_p);
        float a = __expf(dtv * Aval);
        q = fmaf(q, a, dtv * xv * Bv);
        p *= a;
        dt_p += DINNER; xs_p += DINNER; bc_p += XDBL_W;
    }
    int gid = b * (DINNER * DSTATE) + d * DSTATE + s;
    d_Pc[(size_t)ch * NGID + gid] = p;
    d_Qc[(size_t)ch * NGID + gid] = q;
}

// phase 2: serial combine over 16 chunks -> entry state per chunk
__global__ void __launch_bounds__(256)
scan_phase2_kernel()
{
    int gid = blockIdx.x * blockDim.x + threadIdx.x;
    if (gid >= NGID) return;
    float h = 0.f;
#pragma unroll
    for (int ch = 0; ch < NC; ch++) {
        d_hin[(size_t)ch * NGID + gid] = h;
        h = fmaf(d_Pc[(size_t)ch * NGID + gid], h, d_Qc[(size_t)ch * NGID + gid]);
    }
}

// phase 3: replay chunk from exact entry state, produce gated y (hi/lo)
__global__ void __launch_bounds__(256)
scan_phase3_kernel(const float* __restrict__ Dvec)
{
    const int lane = threadIdx.x & 31;
    const int s    = threadIdx.x & 15;
    const int cloc = threadIdx.x >> 4;
    const int b    = blockIdx.x >> 7;
    const int d    = ((blockIdx.x & 127) << 4) + cloc;
    const int ch   = blockIdx.y;
    const int l0   = ch * CL;

    const float Aval = d_A[d * DSTATE + s];
    const float Dv   = Dvec[d];
    int gid = b * (DINNER * DSTATE) + d * DSTATE + s;

    const float* dt_p = d_dt   + ((size_t)b * LL + l0) * DINNER + d;
    const float* xs_p = d_xs   + ((size_t)b * LL + l0) * DINNER + d;
    const float* z_p  = d_xz   + ((size_t)b * LL + l0) * (2 * DINNER) + DINNER + d;
    const float* bc_p = d_xdbl + ((size_t)b * LL + l0) * XDBL_W + DTRANK + s;
    size_t yo = ((size_t)b * LL + l0) * (DINNER / 2) + (d >> 1);

    float h = d_hin[(size_t)ch * NGID + gid];
#pragma unroll 4
    for (int t = 0; t < CL; t++) {
        float dtv = __ldg(dt_p);
        float xv  = __ldg(xs_p);
        float Bv  = __ldg(bc_p);
        float Cv  = __ldg(bc_p + DSTATE);
        float zv  = __ldg(z_p);
        float a = __expf(dtv * Aval);
        h = fmaf(h, a, dtv * xv * Bv);
        float pp = h * Cv;
        pp += __shfl_xor_sync(0xffffffffu, pp, 8);
        pp += __shfl_xor_sync(0xffffffffu, pp, 4);
        pp += __shfl_xor_sync(0xffffffffu, pp, 2);
        pp += __shfl_xor_sync(0xffffffffu, pp, 1);
        float yv = (pp + xv * Dv) * silu_f(zv);
        float yO = __shfl_sync(0xffffffffu, yv, 16);
        if (lane == 0) {
            uint32_t hh, ll;
            split2(yv, yO, hh, ll);
            d_y_hi[yo] = hh; d_y_lo[yo] = ll;
        }
        dt_p += DINNER; xs_p += DINNER; z_p += 2 * DINNER;
        bc_p += XDBL_W; yo += DINNER / 2;
    }
}

// ---------------- launch ----------------
#define SMEM_128x128 (3 * (2 * 128 + 2 * 128) * 12 * 4)  // 73728 B
#define SMEM_128x96  (3 * (2 * 128 + 2 * 96) * 12 * 4)   // 64512 B

extern "C" void kernel_launch(void* const* d_in, const int* in_sizes, int n_in,
                              void* d_out, int out_size)
{
    const float* x         = (const float*)d_in[0];
    const float* W_in      = (const float*)d_in[1];
    const float* conv_w    = (const float*)d_in[2];
    const float* conv_b    = (const float*)d_in[3];
    const float* W_xp      = (const float*)d_in[4];
    const float* W_dt      = (const float*)d_in[5];
    const float* b_dt      = (const float*)d_in[6];
    const float* A_log     = (const float*)d_in[7];
    const float* Dvec      = (const float*)d_in[8];
    const float* W_out_ssm = (const float*)d_in[9];
    const float* W_out     = (const float*)d_in[10];
    const float* b_out     = (const float*)d_in[11];
    float* out = (float*)d_out;

    float *xz, *xdbl, *dt;
    cudaGetSymbolAddress((void**)&xz,   d_xz);
    cudaGetSymbolAddress((void**)&xdbl, d_xdbl);
    cudaGetSymbolAddress((void**)&dt,   d_dt);
    float* part; cudaGetSymbolAddress((void**)&part, d_part);

    uint32_t *x_hi, *x_lo, *Win_hi, *Win_lo, *Wxp_hi, *Wxp_lo, *Wdt_hi, *Wdt_lo;
    uint32_t *Wos_hi, *Wos_lo, *Wo_hi, *Wo_lo, *xs_hi, *xs_lo, *xd_hi, *xd_lo;
    uint32_t *y_hi, *y_lo, *tmp_hi, *tmp_lo;
    cudaGetSymbolAddress((void**)&x_hi,   d_x_hi);   cudaGetSymbolAddress((void**)&x_lo,   d_x_lo);
    cudaGetSymbolAddress((void**)&Win_hi, d_Win_hi); cudaGetSymbolAddress((void**)&Win_lo, d_Win_lo);
    cudaGetSymbolAddress((void**)&Wxp_hi, d_Wxp_hi); cudaGetSymbolAddress((void**)&Wxp_lo, d_Wxp_lo);
    cudaGetSymbolAddress((void**)&Wdt_hi, d_Wdt_hi); cudaGetSymbolAddress((void**)&Wdt_lo, d_Wdt_lo);
    cudaGetSymbolAddress((void**)&Wos_hi, d_Wos_hi); cudaGetSymbolAddress((void**)&Wos_lo, d_Wos_lo);
    cudaGetSymbolAddress((void**)&Wo_hi,  d_Wo_hi);  cudaGetSymbolAddress((void**)&Wo_lo,  d_Wo_lo);
    cudaGetSymbolAddress((void**)&xs_hi,  d_xs_hi);  cudaGetSymbolAddress((void**)&xs_lo,  d_xs_lo);
    cudaGetSymbolAddress((void**)&xd_hi,  d_xd_hi);  cudaGetSymbolAddress((void**)&xd_lo,  d_xd_lo);
    cudaGetSymbolAddress((void**)&y_hi,   d_y_hi);   cudaGetSymbolAddress((void**)&y_lo,   d_y_lo);
    cudaGetSymbolAddress((void**)&tmp_hi, d_tmp_hi); cudaGetSymbolAddress((void**)&tmp_lo, d_tmp_lo);

    // opt in to >48KB dynamic smem (host attribute set; idempotent, capture-safe)
    static bool attr_done = false;
    if (!attr_done) {
        cudaFuncSetAttribute(gemm_bf<128,128,0>, cudaFuncAttributeMaxDynamicSharedMemorySize, SMEM_128x128);
        cudaFuncSetAttribute(gemm_bf<128,128,1>, cudaFuncAttributeMaxDynamicSharedMemorySize, SMEM_128x128);
        cudaFuncSetAttribute(gemm_bf<128,128,2>, cudaFuncAttributeMaxDynamicSharedMemorySize, SMEM_128x128);
        cudaFuncSetAttribute(gemm_bf<128,128,3>, cudaFuncAttributeMaxDynamicSharedMemorySize, SMEM_128x128);
        cudaFuncSetAttribute(gemm_bf<128,96,0>,  cudaFuncAttributeMaxDynamicSharedMemorySize, SMEM_128x96);
        attr_done = true;
    }

    prep_A_kernel<<<(DINNER * DSTATE + 255) / 256, 256>>>(A_log);
    split_all_kernel<<<(SPTOT + 255) / 256, 256>>>(x, W_in, W_xp, W_dt, W_out_ssm, W_out);

    // G1: xz = x @ W_in^T -> [4096,4096] fp32
    gemm_bf<128, 128, 0><<<dim3(2 * DINNER / 128, NROWS / 128, 1), 256, SMEM_128x128>>>(
        x_hi, x_lo, Win_hi, Win_lo, nullptr, xz, nullptr, nullptr,
        DMODEL / 2, DMODEL / 2, DMODEL / 2, 2 * DINNER, 0);

    conv_silu_kernel<<<(NROWS * DINNER) / 256, 256>>>(conv_w, conv_b);

    // G2 split-K: partials[z] = xs @ W_xp^T (chunk z), then reduce
    gemm_bf<128, 96, 0><<<dim3(1, NROWS / 128, G2SPL), 256, SMEM_128x96>>>(
        xs_hi, xs_lo, Wxp_hi, Wxp_lo, nullptr, part, nullptr, nullptr,
        (DINNER / 2) / G2SPL, DINNER / 2, DINNER / 2, XDBL_W, NROWS * XDBL_W);
    g2_reduce_kernel<<<(NROWS * XDBL_W / 2 + 255) / 256, 256>>>();

    // G3: dt = softplus(xdbl[:, :64] @ W_dt^T + b_dt) -> [4096,2048] fp32
    gemm_bf<128, 128, 2><<<dim3(DINNER / 128, NROWS / 128, 1), 256, SMEM_128x128>>>(
        xd_hi, xd_lo, Wdt_hi, Wdt_lo, b_dt, dt, nullptr, nullptr,
        DTRANK / 2, XDBL_W / 2, DTRANK / 2, DINNER, 0);

    // chunked scan: transitions -> combine -> replay with outputs
    scan_phase1_kernel<<<dim3(256, NC), 256>>>();
    scan_phase2_kernel<<<NGID / 256, 256>>>();
    scan_phase3_kernel<<<dim3(256, NC), 256>>>(Dvec);

    // G4: tmp = y @ W_out_ssm^T -> hi/lo packed [4096,512]
    gemm_bf<128, 128, 3><<<dim3(DMODEL / 128, NROWS / 128, 1), 256, SMEM_128x128>>>(
        y_hi, y_lo, Wos_hi, Wos_lo, nullptr, nullptr, tmp_hi, tmp_lo,
        DINNER / 2, DINNER / 2, DINNER / 2, DMODEL / 2, 0);

    // G5: out = tmp @ W_out^T + b_out -> [4096,1024] fp32
    gemm_bf<128, 128, 1><<<dim3(DMODEL / 128, NROWS / 128, 1), 256, SMEM_128x128>>>(
        tmp_hi, tmp_lo, Wo_hi, Wo_lo, b_out, out, nullptr, nullptr,
        DMODEL / 2, DMODEL / 2, DMODEL / 2, DMODEL, 0);
}

// round 7
// speedup vs baseline: 3.1203x; 1.0029x over previous
#include <cuda_runtime.h>
#include <cuda_bf16.h>
#include <cstdint>

// MambaSSMBlock: B=2, L=2048, d_model=1024, d_inner=2048, d_state=16,
// d_conv=4, dt_rank=64
#define BB      2
#define LL      2048
#define DMODEL  1024
#define DINNER  2048
#define DSTATE  16
#define DTRANK  64
#define NROWS   (BB * LL)              // 4096
#define XDBL_W  (DTRANK + 2 * DSTATE)  // 96
#define G2SPL   8                      // split-K chunks for G2
#define NC      16                     // scan chunks along L
#define CL      (LL / NC)              // 128 steps per chunk
#define NGID    (BB * DINNER * DSTATE) // 65536 scan lanes

// ---------------- fp32 scratch ----------------
__device__ float d_xz  [(size_t)NROWS * (2 * DINNER)];
__device__ float d_xs  [(size_t)NROWS * DINNER];
__device__ float d_xdbl[(size_t)NROWS * XDBL_W];
__device__ float d_dt  [(size_t)NROWS * DINNER];
__device__ float d_A   [DINNER * DSTATE];
__device__ float d_part[(size_t)G2SPL * NROWS * XDBL_W];
__device__ float d_Pc  [(size_t)NC * NGID];
__device__ float d_Qc  [(size_t)NC * NGID];
__device__ float d_hin [(size_t)NC * NGID];

// ---------------- packed bf16 hi/lo scratch (pairs along K) ----------------
__device__ uint32_t d_x_hi  [(size_t)NROWS * (DMODEL / 2)];
__device__ uint32_t d_x_lo  [(size_t)NROWS * (DMODEL / 2)];
__device__ uint32_t d_Win_hi[(size_t)(2 * DINNER) * (DMODEL / 2)];
__device__ uint32_t d_Win_lo[(size_t)(2 * DINNER) * (DMODEL / 2)];
__device__ uint32_t d_Wxp_hi[(size_t)XDBL_W * (DINNER / 2)];
__device__ uint32_t d_Wxp_lo[(size_t)XDBL_W * (DINNER / 2)];
__device__ uint32_t d_Wdt_hi[(size_t)DINNER * (DTRANK / 2)];
__device__ uint32_t d_Wdt_lo[(size_t)DINNER * (DTRANK / 2)];
__device__ uint32_t d_Wos_hi[(size_t)DMODEL * (DINNER / 2)];
__device__ uint32_t d_Wos_lo[(size_t)DMODEL * (DINNER / 2)];
__device__ uint32_t d_Wo_hi [(size_t)DMODEL * (DMODEL / 2)];
__device__ uint32_t d_Wo_lo [(size_t)DMODEL * (DMODEL / 2)];
__device__ uint32_t d_xs_hi [(size_t)NROWS * (DINNER / 2)];
__device__ uint32_t d_xs_lo [(size_t)NROWS * (DINNER / 2)];
__device__ uint32_t d_xd_hi [(size_t)NROWS * (XDBL_W / 2)];
__device__ uint32_t d_xd_lo [(size_t)NROWS * (XDBL_W / 2)];
__device__ uint32_t d_y_hi  [(size_t)NROWS * (DINNER / 2)];
__device__ uint32_t d_y_lo  [(size_t)NROWS * (DINNER / 2)];
__device__ uint32_t d_tmp_hi[(size_t)NROWS * (DMODEL / 2)];
__device__ uint32_t d_tmp_lo[(size_t)NROWS * (DMODEL / 2)];

// ---------------- helpers ----------------
__device__ __forceinline__ float silu_f(float v) {
    return v / (1.f + __expf(-v));
}

__device__ __forceinline__ void split2(float x, float y, uint32_t& hi, uint32_t& lo) {
    __nv_bfloat162 h = __floats2bfloat162_rn(x, y);
    float2 hf = __bfloat1622float2(h);
    __nv_bfloat162 l = __floats2bfloat162_rn(x - hf.x, y - hf.y);
    hi = *reinterpret_cast<uint32_t*>(&h);
    lo = *reinterpret_cast<uint32_t*>(&l);
}

__device__ __forceinline__ void mma16(float c[4], const uint32_t a[4], const uint32_t b[2]) {
    asm volatile(
        "mma.sync.aligned.m16n8k16.row.col.f32.bf16.bf16.f32 "
        "{%0,%1,%2,%3},{%4,%5,%6,%7},{%8,%9},{%0,%1,%2,%3};"
        : "+f"(c[0]), "+f"(c[1]), "+f"(c[2]), "+f"(c[3])
        : "r"(a[0]), "r"(a[1]), "r"(a[2]), "r"(a[3]), "r"(b[0]), "r"(b[1]));
}

__device__ __forceinline__ void ldm_x4(uint32_t r[4], uint32_t addr) {
    asm volatile("ldmatrix.sync.aligned.m8n8.x4.shared.b16 {%0,%1,%2,%3}, [%4];"
                 : "=r"(r[0]), "=r"(r[1]), "=r"(r[2]), "=r"(r[3]) : "r"(addr));
}
__device__ __forceinline__ void ldm_x2(uint32_t r[2], uint32_t addr) {
    asm volatile("ldmatrix.sync.aligned.m8n8.x2.shared.b16 {%0,%1}, [%2];"
                 : "=r"(r[0]), "=r"(r[1]) : "r"(addr));
}
__device__ __forceinline__ void cpa16(uint32_t dst, const void* src) {
    asm volatile("cp.async.cg.shared.global [%0], [%1], 16;" :: "r"(dst), "l"(src));
}
__device__ __forceinline__ void cpa_commit() {
    asm volatile("cp.async.commit_group;");
}
template <int N>
__device__ __forceinline__ void cpa_wait() {
    asm volatile("cp.async.wait_group %0;" :: "n"(N));
}

// ---------------- small kernels ----------------
__global__ void prep_A_kernel(const float* __restrict__ A_log) {
    int i = blockIdx.x * blockDim.x + threadIdx.x;
    if (i < DINNER * DSTATE) d_A[i] = -expf(A_log[i]);
}

// fused split of all six fp32->bf16(hi/lo) conversions
#define SP0 (NROWS * DMODEL / 2)
#define SP1 (2 * DINNER * DMODEL / 2)
#define SP2 (XDBL_W * DINNER / 2)
#define SP3 (DINNER * DTRANK / 2)
#define SP4 (DMODEL * DINNER / 2)
#define SP5 (DMODEL * DMODEL / 2)
#define SPTOT (SP0 + SP1 + SP2 + SP3 + SP4 + SP5)

__global__ void __launch_bounds__(256)
split_all_kernel(const float* __restrict__ x, const float* __restrict__ Win,
                 const float* __restrict__ Wxp, const float* __restrict__ Wdt,
                 const float* __restrict__ Wos, const float* __restrict__ Wo)
{
    int i = blockIdx.x * blockDim.x + threadIdx.x;
    if (i >= SPTOT) return;
    const float* src; uint32_t *hi, *lo; int off;
    if (i < SP0)                       { src = x;   hi = d_x_hi;   lo = d_x_lo;   off = i; }
    else if (i < SP0+SP1)              { src = Win; hi = d_Win_hi; lo = d_Win_lo; off = i - SP0; }
    else if (i < SP0+SP1+SP2)          { src = Wxp; hi = d_Wxp_hi; lo = d_Wxp_lo; off = i - (SP0+SP1); }
    else if (i < SP0+SP1+SP2+SP3)      { src = Wdt; hi = d_Wdt_hi; lo = d_Wdt_lo; off = i - (SP0+SP1+SP2); }
    else if (i < SP0+SP1+SP2+SP3+SP4)  { src = Wos; hi = d_Wos_hi; lo = d_Wos_lo; off = i - (SP0+SP1+SP2+SP3); }
    else                               { src = Wo;  hi = d_Wo_hi;  lo = d_Wo_lo;  off = i - (SP0+SP1+SP2+SP3+SP4); }
    float2 v = reinterpret_cast<const float2*>(src)[off];
    split2(v.x, v.y, hi[off], lo[off]);
}

// ===== bf16 split tensor-core GEMM, 4-stage cp.async, 1 sync per 2 k-iters ===
// C[M,N] = A[M,K] @ W[N,K]^T, packed bf16 hi/lo inputs. Dynamic smem.
// EPI: 0 fp32, 1 fp32+bias, 2 softplus(v+bias), 3 write packed hi/lo.
template<int BM, int BN, int EPI>
__global__ void __launch_bounds__(256, 2)
gemm_bf(const uint32_t* __restrict__ Ah, const uint32_t* __restrict__ Al,
        const uint32_t* __restrict__ Bh, const uint32_t* __restrict__ Bl,
        const float* __restrict__ bias, float* __restrict__ C,
        uint32_t* __restrict__ Chi, uint32_t* __restrict__ Clo,
        int kpairs, int lda, int ldb, int ldc, int c_chunk_stride)
{
    constexpr int P = 12;                        // smem pitch (words): 8 data + 4 pad
    constexpr int STAGE = (2 * BM + 2 * BN) * P; // words per stage
    constexpr int WARPS_N = 4;
    constexpr int WM = BM / 2, WN = BN / WARPS_N;
    constexpr int MT = WM / 16, NT = WN / 8;

    extern __shared__ __align__(16) uint32_t sm[];
    const uint32_t smu = (uint32_t)__cvta_generic_to_shared(sm);

    const int tid = threadIdx.x;
    const int warp = tid >> 5, lane = tid & 31;
    const int wm = (warp / WARPS_N) * WM;
    const int wn = (warp % WARPS_N) * WN;

    float c[MT][NT][4];
#pragma unroll
    for (int i = 0; i < MT; i++)
#pragma unroll
        for (int j = 0; j < NT; j++)
#pragma unroll
            for (int t = 0; t < 4; t++) c[i][j][t] = 0.f;

    const size_t arow0 = (size_t)blockIdx.y * BM;
    const size_t brow0 = (size_t)blockIdx.x * BN;
    const int kp_base = blockIdx.z * kpairs;
    if (EPI == 0 && c_chunk_stride) C += (size_t)blockIdx.z * c_chunk_stride;

    auto load_stage = [&](int s, int kp) {
        uint32_t base = smu + s * STAGE * 4;
#pragma unroll 1
        for (int i = tid; i < BM * 2; i += 256) {
            int r = i >> 1, cg = (i & 1) * 4;
            size_t go = (arow0 + r) * (size_t)lda + kp + cg;
            cpa16(base + (r * P + cg) * 4, Ah + go);
            cpa16(base + (BM * P + r * P + cg) * 4, Al + go);
        }
#pragma unroll 1
        for (int i = tid; i < BN * 2; i += 256) {
            int r = i >> 1, cg = (i & 1) * 4;
            size_t go = (brow0 + r) * (size_t)ldb + kp + cg;
            cpa16(base + (2 * BM * P + r * P + cg) * 4, Bh + go);
            cpa16(base + ((2 * BM + BN) * P + r * P + cg) * 4, Bl + go);
        }
    };

    const int la = lane & 15, lg = lane >> 4;
    const int lb = lane & 7, lbg = (lane >> 3) & 1;

    auto compute_stage = [&](int st) {
        const uint32_t aHi = smu + (st * STAGE) * 4;
        const uint32_t aLo = aHi + BM * P * 4;
        const uint32_t bHi = aHi + 2 * BM * P * 4;
        const uint32_t bLo = bHi + BN * P * 4;

        uint32_t ah[MT][4], al[MT][4], bh[NT][2], bl[NT][2];
#pragma unroll
        for (int mt = 0; mt < MT; mt++) {
            uint32_t off = ((wm + mt * 16 + la) * P + lg * 4) * 4;
            ldm_x4(ah[mt], aHi + off);
            ldm_x4(al[mt], aLo + off);
        }
#pragma unroll
        for (int nt = 0; nt < NT; nt++) {
            uint32_t off = ((wn + nt * 8 + lb) * P + lbg * 4) * 4;
            ldm_x2(bh[nt], bHi + off);
            ldm_x2(bl[nt], bLo + off);
        }
#pragma unroll
        for (int mt = 0; mt < MT; mt++)
#pragma unroll
            for (int nt = 0; nt < NT; nt++) {
                mma16(c[mt][nt], ah[mt], bh[nt]);
                mma16(c[mt][nt], ah[mt], bl[nt]);
                mma16(c[mt][nt], al[mt], bh[nt]);
            }
    };

    const int nk = kpairs / 8;                   // K/16 iterations (even for all uses)
    load_stage(0, kp_base);
    load_stage(1, kp_base + 8);
    cpa_commit();

    for (int kt = 0; kt < nk; kt += 2) {
        cpa_wait<0>();
        __syncthreads();
        if (kt + 2 < nk) {
            load_stage((kt + 2) & 3, kp_base + (kt + 2) * 8);
            load_stage((kt + 3) & 3, kp_base + (kt + 3) * 8);
            cpa_commit();
        }
        compute_stage(kt & 3);
        compute_stage((kt + 1) & 3);
    }

    // ---------------- epilogue ----------------
#pragma unroll
    for (int mt = 0; mt < MT; mt++) {
#pragma unroll
        for (int nt = 0; nt < NT; nt++) {
            int m0 = blockIdx.y * BM + wm + mt * 16 + (lane >> 2);
            int n  = blockIdx.x * BN + wn + nt * 8 + 2 * (lane & 3);
            float v0 = c[mt][nt][0], v1 = c[mt][nt][1];
            float v2 = c[mt][nt][2], v3 = c[mt][nt][3];
            if (EPI == 1 || EPI == 2) {
                float2 bv = *(const float2*)(bias + n);
                v0 += bv.x; v1 += bv.y; v2 += bv.x; v3 += bv.y;
            }
            if (EPI == 2) {
                v0 = (v0 > 20.f) ? v0 : log1pf(__expf(v0));
                v1 = (v1 > 20.f) ? v1 : log1pf(__expf(v1));
                v2 = (v2 > 20.f) ? v2 : log1pf(__expf(v2));
                v3 = (v3 > 20.f) ? v3 : log1pf(__expf(v3));
            }
            if (EPI <= 2) {
                *(float2*)(C + (size_t)m0 * ldc + n)       = make_float2(v0, v1);
                *(float2*)(C + (size_t)(m0 + 8) * ldc + n) = make_float2(v2, v3);
            } else {
                uint32_t h, l;
                split2(v0, v1, h, l);
                Chi[(size_t)m0 * ldc + (n >> 1)] = h;
                Clo[(size_t)m0 * ldc + (n >> 1)] = l;
                split2(v2, v3, h, l);
                Chi[(size_t)(m0 + 8) * ldc + (n >> 1)] = h;
                Clo[(size_t)(m0 + 8) * ldc + (n >> 1)] = l;
            }
        }
    }
}

// ---------------- G2 split-K reduce ----------------
__global__ void g2_reduce_kernel() {
    int i = blockIdx.x * blockDim.x + threadIdx.x;
    if (i < NROWS * XDBL_W / 2) {
        float s0 = 0.f, s1 = 0.f;
#pragma unroll
        for (int z = 0; z < G2SPL; z++) {
            float2 v = reinterpret_cast<const float2*>(d_part + (size_t)z * NROWS * XDBL_W)[i];
            s0 += v.x; s1 += v.y;
        }
        reinterpret_cast<float2*>(d_xdbl)[i] = make_float2(s0, s1);
        split2(s0, s1, d_xd_hi[i], d_xd_lo[i]);
    }
}

// ---------------- causal depthwise conv (k=4) + SiLU ----------------
__global__ void __launch_bounds__(256)
conv_silu_kernel(const float* __restrict__ conv_w, const float* __restrict__ conv_b)
{
    int idx = blockIdx.x * blockDim.x + threadIdx.x;
    int d     = idx & (DINNER - 1);
    int rowid = idx >> 11;
    int l     = rowid & (LL - 1);
    const float* base = d_xz + (size_t)rowid * (2 * DINNER) + d;
    const float4 w = *(const float4*)(conv_w + d * 4);
    float acc = conv_b[d];
    if (l >= 3) acc = fmaf(w.x, base[-3 * (2 * DINNER)], acc);
    if (l >= 2) acc = fmaf(w.y, base[-2 * (2 * DINNER)], acc);
    if (l >= 1) acc = fmaf(w.z, base[-1 * (2 * DINNER)], acc);
    acc = fmaf(w.w, base[0], acc);
    float r = silu_f(acc);
    d_xs[(size_t)rowid * DINNER + d] = r;
    float rn = __shfl_xor_sync(0xffffffffu, r, 1);
    if ((d & 1) == 0) {
        uint32_t h, lo;
        split2(r, rn, h, lo);
        size_t o = (size_t)rowid * (DINNER / 2) + (d >> 1);
        d_xs_hi[o] = h; d_xs_lo[o] = lo;
    }
}

// ---------------- chunked selective scan ----------------
__global__ void __launch_bounds__(256)
scan_phase1_kernel()
{
    const int s    = threadIdx.x & 15;
    const int cloc = threadIdx.x >> 4;
    const int b    = blockIdx.x >> 7;
    const int d    = ((blockIdx.x & 127) << 4) + cloc;
    const int ch   = blockIdx.y;
    const int l0   = ch * CL;

    const float Aval = d_A[d * DSTATE + s];
    const float* dt_p = d_dt   + ((size_t)b * LL + l0) * DINNER + d;
    const float* xs_p = d_xs   + ((size_t)b * LL + l0) * DINNER + d;
    const float* bc_p = d_xdbl + ((size_t)b * LL + l0) * XDBL_W + DTRANK + s;

    float p = 1.f, q = 0.f;
#pragma unroll 4
    for (int t = 0; t < CL; t++) {
        float dtv = __ldg(dt_p);
        float xv  = __ldg(xs_p);
        float Bv  = __ldg(bc_p);
        float a = __expf(dtv * Aval);
        q = fmaf(q, a, dtv * xv * Bv);
        p *= a;
        dt_p += DINNER; xs_p += DINNER; bc_p += XDBL_W;
    }
    int gid = b * (DINNER * DSTATE) + d * DSTATE + s;
    d_Pc[(size_t)ch * NGID + gid] = p;
    d_Qc[(size_t)ch * NGID + gid] = q;
}

__global__ void __launch_bounds__(256)
scan_phase2_kernel()
{
    int gid = blockIdx.x * blockDim.x + threadIdx.x;
    if (gid >= NGID) return;
    float h = 0.f;
#pragma unroll
    for (int ch = 0; ch < NC; ch++) {
        d_hin[(size_t)ch * NGID + gid] = h;
        h = fmaf(d_Pc[(size_t)ch * NGID + gid], h, d_Qc[(size_t)ch * NGID + gid]);
    }
}

__global__ void __launch_bounds__(256)
scan_phase3_kernel(const float* __restrict__ Dvec)
{
    const int lane = threadIdx.x & 31;
    const int s    = threadIdx.x & 15;
    const int cloc = threadIdx.x >> 4;
    const int b    = blockIdx.x >> 7;
    const int d    = ((blockIdx.x & 127) << 4) + cloc;
    const int ch   = blockIdx.y;
    const int l0   = ch * CL;

    const float Aval = d_A[d * DSTATE + s];
    const float Dv   = Dvec[d];
    int gid = b * (DINNER * DSTATE) + d * DSTATE + s;

    const float* dt_p = d_dt   + ((size_t)b * LL + l0) * DINNER + d;
    const float* xs_p = d_xs   + ((size_t)b * LL + l0) * DINNER + d;
    const float* z_p  = d_xz   + ((size_t)b * LL + l0) * (2 * DINNER) + DINNER + d;
    const float* bc_p = d_xdbl + ((size_t)b * LL + l0) * XDBL_W + DTRANK + s;
    size_t yo = ((size_t)b * LL + l0) * (DINNER / 2) + (d >> 1);

    float h = d_hin[(size_t)ch * NGID + gid];
#pragma unroll 4
    for (int t = 0; t < CL; t++) {
        float dtv = __ldg(dt_p);
        float xv  = __ldg(xs_p);
        float Bv  = __ldg(bc_p);
        float Cv  = __ldg(bc_p + DSTATE);
        float zv  = __ldg(z_p);
        float a = __expf(dtv * Aval);
        h = fmaf(h, a, dtv * xv * Bv);
        float pp = h * Cv;
        pp += __shfl_xor_sync(0xffffffffu, pp, 8);
        pp += __shfl_xor_sync(0xffffffffu, pp, 4);
        pp += __shfl_xor_sync(0xffffffffu, pp, 2);
        pp += __shfl_xor_sync(0xffffffffu, pp, 1);
        float yv = (pp + xv * Dv) * silu_f(zv);
        float yO = __shfl_sync(0xffffffffu, yv, 16);
        if (lane == 0) {
            uint32_t hh, ll;
            split2(yv, yO, hh, ll);
            d_y_hi[yo] = hh; d_y_lo[yo] = ll;
        }
        dt_p += DINNER; xs_p += DINNER; z_p += 2 * DINNER;
        bc_p += XDBL_W; yo += DINNER / 2;
    }
}

// ---------------- launch ----------------
#define SMEM_128x128 (4 * (2 * 128 + 2 * 128) * 12 * 4)  // 98304 B
#define SMEM_128x96  (4 * (2 * 128 + 2 * 96) * 12 * 4)   // 86016 B

extern "C" void kernel_launch(void* const* d_in, const int* in_sizes, int n_in,
                              void* d_out, int out_size)
{
    const float* x         = (const float*)d_in[0];
    const float* W_in      = (const float*)d_in[1];
    const float* conv_w    = (const float*)d_in[2];
    const float* conv_b    = (const float*)d_in[3];
    const float* W_xp      = (const float*)d_in[4];
    const float* W_dt      = (const float*)d_in[5];
    const float* b_dt      = (const float*)d_in[6];
    const float* A_log     = (const float*)d_in[7];
    const float* Dvec      = (const float*)d_in[8];
    const float* W_out_ssm = (const float*)d_in[9];
    const float* W_out     = (const float*)d_in[10];
    const float* b_out     = (const float*)d_in[11];
    float* out = (float*)d_out;

    float *xz, *xdbl, *dt;
    cudaGetSymbolAddress((void**)&xz,   d_xz);
    cudaGetSymbolAddress((void**)&xdbl, d_xdbl);
    cudaGetSymbolAddress((void**)&dt,   d_dt);
    float* part; cudaGetSymbolAddress((void**)&part, d_part);

    uint32_t *x_hi, *x_lo, *Win_hi, *Win_lo, *Wxp_hi, *Wxp_lo, *Wdt_hi, *Wdt_lo;
    uint32_t *Wos_hi, *Wos_lo, *Wo_hi, *Wo_lo, *xs_hi, *xs_lo, *xd_hi, *xd_lo;
    uint32_t *y_hi, *y_lo, *tmp_hi, *tmp_lo;
    cudaGetSymbolAddress((void**)&x_hi,   d_x_hi);   cudaGetSymbolAddress((void**)&x_lo,   d_x_lo);
    cudaGetSymbolAddress((void**)&Win_hi, d_Win_hi); cudaGetSymbolAddress((void**)&Win_lo, d_Win_lo);
    cudaGetSymbolAddress((void**)&Wxp_hi, d_Wxp_hi); cudaGetSymbolAddress((void**)&Wxp_lo, d_Wxp_lo);
    cudaGetSymbolAddress((void**)&Wdt_hi, d_Wdt_hi); cudaGetSymbolAddress((void**)&Wdt_lo, d_Wdt_lo);
    cudaGetSymbolAddress((void**)&Wos_hi, d_Wos_hi); cudaGetSymbolAddress((void**)&Wos_lo, d_Wos_lo);
    cudaGetSymbolAddress((void**)&Wo_hi,  d_Wo_hi);  cudaGetSymbolAddress((void**)&Wo_lo,  d_Wo_lo);
    cudaGetSymbolAddress((void**)&xs_hi,  d_xs_hi);  cudaGetSymbolAddress((void**)&xs_lo,  d_xs_lo);
    cudaGetSymbolAddress((void**)&xd_hi,  d_xd_hi);  cudaGetSymbolAddress((void**)&xd_lo,  d_xd_lo);
    cudaGetSymbolAddress((void**)&y_hi,   d_y_hi);   cudaGetSymbolAddress((void**)&y_lo,   d_y_lo);
    cudaGetSymbolAddress((void**)&tmp_hi, d_tmp_hi); cudaGetSymbolAddress((void**)&tmp_lo, d_tmp_lo);

    // opt in to >48KB dynamic smem (host attribute set; idempotent, capture-safe)
    static bool attr_done = false;
    if (!attr_done) {
        cudaFuncSetAttribute(gemm_bf<128,128,0>, cudaFuncAttributeMaxDynamicSharedMemorySize, SMEM_128x128);
        cudaFuncSetAttribute(gemm_bf<128,128,1>, cudaFuncAttributeMaxDynamicSharedMemorySize, SMEM_128x128);
        cudaFuncSetAttribute(gemm_bf<128,128,2>, cudaFuncAttributeMaxDynamicSharedMemorySize, SMEM_128x128);
        cudaFuncSetAttribute(gemm_bf<128,128,3>, cudaFuncAttributeMaxDynamicSharedMemorySize, SMEM_128x128);
        cudaFuncSetAttribute(gemm_bf<128,96,0>,  cudaFuncAttributeMaxDynamicSharedMemorySize, SMEM_128x96);
        attr_done = true;
    }

    prep_A_kernel<<<(DINNER * DSTATE + 255) / 256, 256>>>(A_log);
    split_all_kernel<<<(SPTOT + 255) / 256, 256>>>(x, W_in, W_xp, W_dt, W_out_ssm, W_out);

    // G1: xz = x @ W_in^T -> [4096,4096] fp32
    gemm_bf<128, 128, 0><<<dim3(2 * DINNER / 128, NROWS / 128, 1), 256, SMEM_128x128>>>(
        x_hi, x_lo, Win_hi, Win_lo, nullptr, xz, nullptr, nullptr,
        DMODEL / 2, DMODEL / 2, DMODEL / 2, 2 * DINNER, 0);

    conv_silu_kernel<<<(NROWS * DINNER) / 256, 256>>>(conv_w, conv_b);

    // G2 split-K: partials[z] = xs @ W_xp^T (chunk z), then reduce
    gemm_bf<128, 96, 0><<<dim3(1, NROWS / 128, G2SPL), 256, SMEM_128x96>>>(
        xs_hi, xs_lo, Wxp_hi, Wxp_lo, nullptr, part, nullptr, nullptr,
        (DINNER / 2) / G2SPL, DINNER / 2, DINNER / 2, XDBL_W, NROWS * XDBL_W);
    g2_reduce_kernel<<<(NROWS * XDBL_W / 2 + 255) / 256, 256>>>();

    // G3: dt = softplus(xdbl[:, :64] @ W_dt^T + b_dt) -> [4096,2048] fp32
    gemm_bf<128, 128, 2><<<dim3(DINNER / 128, NROWS / 128, 1), 256, SMEM_128x128>>>(
        xd_hi, xd_lo, Wdt_hi, Wdt_lo, b_dt, dt, nullptr, nullptr,
        DTRANK / 2, XDBL_W / 2, DTRANK / 2, DINNER, 0);

    // chunked scan: transitions -> combine -> replay with outputs
    scan_phase1_kernel<<<dim3(256, NC), 256>>>();
    scan_phase2_kernel<<<NGID / 256, 256>>>();
    scan_phase3_kernel<<<dim3(256, NC), 256>>>(Dvec);

    // G4: tmp = y @ W_out_ssm^T -> hi/lo packed [4096,512]
    gemm_bf<128, 128, 3><<<dim3(DMODEL / 128, NROWS / 128, 1), 256, SMEM_128x128>>>(
        y_hi, y_lo, Wos_hi, Wos_lo, nullptr, nullptr, tmp_hi, tmp_lo,
        DINNER / 2, DINNER / 2, DINNER / 2, DMODEL / 2, 0);

    // G5: out = tmp @ W_out^T + b_out -> [4096,1024] fp32
    gemm_bf<128, 128, 1><<<dim3(DMODEL / 128, NROWS / 128, 1), 256, SMEM_128x128>>>(
        tmp_hi, tmp_lo, Wo_hi, Wo_lo, b_out, out, nullptr, nullptr,
        DMODEL / 2, DMODEL / 2, DMODEL / 2, DMODEL, 0);
}

// round 8
// speedup vs baseline: 3.9801x; 1.2756x over previous
#include <cuda_runtime.h>
#include <cuda_bf16.h>
#include <cstdint>

// MambaSSMBlock: B=2, L=2048, d_model=1024, d_inner=2048, d_state=16,
// d_conv=4, dt_rank=64
#define BB      2
#define LL      2048
#define DMODEL  1024
#define DINNER  2048
#define DSTATE  16
#define DTRANK  64
#define NROWS   (BB * LL)              // 4096
#define XDBL_W  (DTRANK + 2 * DSTATE)  // 96
#define G2SPL   8                      // split-K chunks for G2
#define NC      32                     // scan chunks along L
#define CL      (LL / NC)              // 64 steps per chunk
#define NGID    (BB * DINNER * DSTATE) // 65536 scan lanes

// ---------------- fp32 scratch ----------------
__device__ float d_xz  [(size_t)NROWS * (2 * DINNER)];
__device__ float d_xs  [(size_t)NROWS * DINNER];
__device__ float d_xdbl[(size_t)NROWS * XDBL_W];
__device__ float d_dt  [(size_t)NROWS * DINNER];
__device__ float d_A   [DINNER * DSTATE];
__device__ float d_part[(size_t)G2SPL * NROWS * XDBL_W];
__device__ float d_Pc  [(size_t)NC * NGID];
__device__ float d_Qc  [(size_t)NC * NGID];
__device__ float d_hin [(size_t)NC * NGID];

// ---------------- packed bf16 hi/lo scratch (pairs along K) ----------------
__device__ uint32_t d_x_hi  [(size_t)NROWS * (DMODEL / 2)];
__device__ uint32_t d_x_lo  [(size_t)NROWS * (DMODEL / 2)];
__device__ uint32_t d_Win_hi[(size_t)(2 * DINNER) * (DMODEL / 2)];
__device__ uint32_t d_Win_lo[(size_t)(2 * DINNER) * (DMODEL / 2)];
__device__ uint32_t d_Wxp_hi[(size_t)XDBL_W * (DINNER / 2)];
__device__ uint32_t d_Wxp_lo[(size_t)XDBL_W * (DINNER / 2)];
__device__ uint32_t d_Wdt_hi[(size_t)DINNER * (DTRANK / 2)];
__device__ uint32_t d_Wdt_lo[(size_t)DINNER * (DTRANK / 2)];
__device__ uint32_t d_Wos_hi[(size_t)DMODEL * (DINNER / 2)];
__device__ uint32_t d_Wos_lo[(size_t)DMODEL * (DINNER / 2)];
__device__ uint32_t d_Wo_hi [(size_t)DMODEL * (DMODEL / 2)];
__device__ uint32_t d_Wo_lo [(size_t)DMODEL * (DMODEL / 2)];
__device__ uint32_t d_xs_hi [(size_t)NROWS * (DINNER / 2)];
__device__ uint32_t d_xs_lo [(size_t)NROWS * (DINNER / 2)];
__device__ uint32_t d_xd_hi [(size_t)NROWS * (XDBL_W / 2)];
__device__ uint32_t d_xd_lo [(size_t)NROWS * (XDBL_W / 2)];
__device__ uint32_t d_y_hi  [(size_t)NROWS * (DINNER / 2)];
__device__ uint32_t d_y_lo  [(size_t)NROWS * (DINNER / 2)];
__device__ uint32_t d_tmp_hi[(size_t)NROWS * (DMODEL / 2)];
__device__ uint32_t d_tmp_lo[(size_t)NROWS * (DMODEL / 2)];

// ---------------- helpers ----------------
__device__ __forceinline__ float silu_f(float v) {
    return v / (1.f + __expf(-v));
}

__device__ __forceinline__ void split2(float x, float y, uint32_t& hi, uint32_t& lo) {
    __nv_bfloat162 h = __floats2bfloat162_rn(x, y);
    float2 hf = __bfloat1622float2(h);
    __nv_bfloat162 l = __floats2bfloat162_rn(x - hf.x, y - hf.y);
    hi = *reinterpret_cast<uint32_t*>(&h);
    lo = *reinterpret_cast<uint32_t*>(&l);
}

__device__ __forceinline__ void mma16(float c[4], const uint32_t a[4], const uint32_t b[2]) {
    asm volatile(
        "mma.sync.aligned.m16n8k16.row.col.f32.bf16.bf16.f32 "
        "{%0,%1,%2,%3},{%4,%5,%6,%7},{%8,%9},{%0,%1,%2,%3};"
        : "+f"(c[0]), "+f"(c[1]), "+f"(c[2]), "+f"(c[3])
        : "r"(a[0]), "r"(a[1]), "r"(a[2]), "r"(a[3]), "r"(b[0]), "r"(b[1]));
}

__device__ __forceinline__ void ldm_x4(uint32_t r[4], uint32_t addr) {
    asm volatile("ldmatrix.sync.aligned.m8n8.x4.shared.b16 {%0,%1,%2,%3}, [%4];"
                 : "=r"(r[0]), "=r"(r[1]), "=r"(r[2]), "=r"(r[3]) : "r"(addr));
}
__device__ __forceinline__ void ldm_x2(uint32_t r[2], uint32_t addr) {
    asm volatile("ldmatrix.sync.aligned.m8n8.x2.shared.b16 {%0,%1}, [%2];"
                 : "=r"(r[0]), "=r"(r[1]) : "r"(addr));
}
__device__ __forceinline__ void cpa16(uint32_t dst, const void* src) {
    asm volatile("cp.async.cg.shared.global [%0], [%1], 16;" :: "r"(dst), "l"(src));
}
__device__ __forceinline__ void cpa_commit() {
    asm volatile("cp.async.commit_group;");
}
template <int N>
__device__ __forceinline__ void cpa_wait() {
    asm volatile("cp.async.wait_group %0;" :: "n"(N));
}

// ---------------- fused split (+ A prep) ----------------
#define SP0 (NROWS * DMODEL / 2)
#define SP1 (2 * DINNER * DMODEL / 2)
#define SP2 (XDBL_W * DINNER / 2)
#define SP3 (DINNER * DTRANK / 2)
#define SP4 (DMODEL * DINNER / 2)
#define SP5 (DMODEL * DMODEL / 2)
#define SPTOT (SP0 + SP1 + SP2 + SP3 + SP4 + SP5)
#define SPA   (DINNER * DSTATE)

__global__ void __launch_bounds__(256)
split_all_kernel(const float* __restrict__ x, const float* __restrict__ Win,
                 const float* __restrict__ Wxp, const float* __restrict__ Wdt,
                 const float* __restrict__ Wos, const float* __restrict__ Wo,
                 const float* __restrict__ A_log)
{
    int i = blockIdx.x * blockDim.x + threadIdx.x;
    if (i >= SPTOT) {
        int j = i - SPTOT;
        if (j < SPA) d_A[j] = -expf(A_log[j]);
        return;
    }
    const float* src; uint32_t *hi, *lo; int off;
    if (i < SP0)                       { src = x;   hi = d_x_hi;   lo = d_x_lo;   off = i; }
    else if (i < SP0+SP1)              { src = Win; hi = d_Win_hi; lo = d_Win_lo; off = i - SP0; }
    else if (i < SP0+SP1+SP2)          { src = Wxp; hi = d_Wxp_hi; lo = d_Wxp_lo; off = i - (SP0+SP1); }
    else if (i < SP0+SP1+SP2+SP3)      { src = Wdt; hi = d_Wdt_hi; lo = d_Wdt_lo; off = i - (SP0+SP1+SP2); }
    else if (i < SP0+SP1+SP2+SP3+SP4)  { src = Wos; hi = d_Wos_hi; lo = d_Wos_lo; off = i - (SP0+SP1+SP2+SP3); }
    else                               { src = Wo;  hi = d_Wo_hi;  lo = d_Wo_lo;  off = i - (SP0+SP1+SP2+SP3+SP4); }
    float2 v = reinterpret_cast<const float2*>(src)[off];
    split2(v.x, v.y, hi[off], lo[off]);
}

// ===== bf16 split tensor-core GEMM, 4-stage cp.async, 1 sync per 2 k-iters ===
template<int BM, int BN, int EPI>
__global__ void __launch_bounds__(256, 2)
gemm_bf(const uint32_t* __restrict__ Ah, const uint32_t* __restrict__ Al,
        const uint32_t* __restrict__ Bh, const uint32_t* __restrict__ Bl,
        const float* __restrict__ bias, float* __restrict__ C,
        uint32_t* __restrict__ Chi, uint32_t* __restrict__ Clo,
        int kpairs, int lda, int ldb, int ldc, int c_chunk_stride)
{
    constexpr int P = 12;
    constexpr int STAGE = (2 * BM + 2 * BN) * P;
    constexpr int WARPS_N = 4;
    constexpr int WM = BM / 2, WN = BN / WARPS_N;
    constexpr int MT = WM / 16, NT = WN / 8;

    extern __shared__ __align__(16) uint32_t sm[];
    const uint32_t smu = (uint32_t)__cvta_generic_to_shared(sm);

    const int tid = threadIdx.x;
    const int warp = tid >> 5, lane = tid & 31;
    const int wm = (warp / WARPS_N) * WM;
    const int wn = (warp % WARPS_N) * WN;

    float c[MT][NT][4];
#pragma unroll
    for (int i = 0; i < MT; i++)
#pragma unroll
        for (int j = 0; j < NT; j++)
#pragma unroll
            for (int t = 0; t < 4; t++) c[i][j][t] = 0.f;

    const size_t arow0 = (size_t)blockIdx.y * BM;
    const size_t brow0 = (size_t)blockIdx.x * BN;
    const int kp_base = blockIdx.z * kpairs;
    if (EPI == 0 && c_chunk_stride) C += (size_t)blockIdx.z * c_chunk_stride;

    auto load_stage = [&](int s, int kp) {
        uint32_t base = smu + s * STAGE * 4;
#pragma unroll 1
        for (int i = tid; i < BM * 2; i += 256) {
            int r = i >> 1, cg = (i & 1) * 4;
            size_t go = (arow0 + r) * (size_t)lda + kp + cg;
            cpa16(base + (r * P + cg) * 4, Ah + go);
            cpa16(base + (BM * P + r * P + cg) * 4, Al + go);
        }
#pragma unroll 1
        for (int i = tid; i < BN * 2; i += 256) {
            int r = i >> 1, cg = (i & 1) * 4;
            size_t go = (brow0 + r) * (size_t)ldb + kp + cg;
            cpa16(base + (2 * BM * P + r * P + cg) * 4, Bh + go);
            cpa16(base + ((2 * BM + BN) * P + r * P + cg) * 4, Bl + go);
        }
    };

    const int la = lane & 15, lg = lane >> 4;
    const int lb = lane & 7, lbg = (lane >> 3) & 1;

    auto compute_stage = [&](int st) {
        const uint32_t aHi = smu + (st * STAGE) * 4;
        const uint32_t aLo = aHi + BM * P * 4;
        const uint32_t bHi = aHi + 2 * BM * P * 4;
        const uint32_t bLo = bHi + BN * P * 4;

        uint32_t ah[MT][4], al[MT][4], bh[NT][2], bl[NT][2];
#pragma unroll
        for (int mt = 0; mt < MT; mt++) {
            uint32_t off = ((wm + mt * 16 + la) * P + lg * 4) * 4;
            ldm_x4(ah[mt], aHi + off);
            ldm_x4(al[mt], aLo + off);
        }
#pragma unroll
        for (int nt = 0; nt < NT; nt++) {
            uint32_t off = ((wn + nt * 8 + lb) * P + lbg * 4) * 4;
            ldm_x2(bh[nt], bHi + off);
            ldm_x2(bl[nt], bLo + off);
        }
#pragma unroll
        for (int mt = 0; mt < MT; mt++)
#pragma unroll
            for (int nt = 0; nt < NT; nt++) {
                mma16(c[mt][nt], ah[mt], bh[nt]);
                mma16(c[mt][nt], ah[mt], bl[nt]);
                mma16(c[mt][nt], al[mt], bh[nt]);
            }
    };

    const int nk = kpairs / 8;
    load_stage(0, kp_base);
    load_stage(1, kp_base + 8);
    cpa_commit();

    for (int kt = 0; kt < nk; kt += 2) {
        cpa_wait<0>();
        __syncthreads();
        if (kt + 2 < nk) {
            load_stage((kt + 2) & 3, kp_base + (kt + 2) * 8);
            load_stage((kt + 3) & 3, kp_base + (kt + 3) * 8);
            cpa_commit();
        }
        compute_stage(kt & 3);
        compute_stage((kt + 1) & 3);
    }

#pragma unroll
    for (int mt = 0; mt < MT; mt++) {
#pragma unroll
        for (int nt = 0; nt < NT; nt++) {
            int m0 = blockIdx.y * BM + wm + mt * 16 + (lane >> 2);
            int n  = blockIdx.x * BN + wn + nt * 8 + 2 * (lane & 3);
            float v0 = c[mt][nt][0], v1 = c[mt][nt][1];
            float v2 = c[mt][nt][2], v3 = c[mt][nt][3];
            if (EPI == 1 || EPI == 2) {
                float2 bv = *(const float2*)(bias + n);
                v0 += bv.x; v1 += bv.y; v2 += bv.x; v3 += bv.y;
            }
            if (EPI == 2) {
                v0 = (v0 > 20.f) ? v0 : log1pf(__expf(v0));
                v1 = (v1 > 20.f) ? v1 : log1pf(__expf(v1));
                v2 = (v2 > 20.f) ? v2 : log1pf(__expf(v2));
                v3 = (v3 > 20.f) ? v3 : log1pf(__expf(v3));
            }
            if (EPI <= 2) {
                *(float2*)(C + (size_t)m0 * ldc + n)       = make_float2(v0, v1);
                *(float2*)(C + (size_t)(m0 + 8) * ldc + n) = make_float2(v2, v3);
            } else {
                uint32_t h, l;
                split2(v0, v1, h, l);
                Chi[(size_t)m0 * ldc + (n >> 1)] = h;
                Clo[(size_t)m0 * ldc + (n >> 1)] = l;
                split2(v2, v3, h, l);
                Chi[(size_t)(m0 + 8) * ldc + (n >> 1)] = h;
                Clo[(size_t)(m0 + 8) * ldc + (n >> 1)] = l;
            }
        }
    }
}

// ---------------- G2 split-K reduce ----------------
__global__ void g2_reduce_kernel() {
    int i = blockIdx.x * blockDim.x + threadIdx.x;
    if (i < NROWS * XDBL_W / 2) {
        float s0 = 0.f, s1 = 0.f;
#pragma unroll
        for (int z = 0; z < G2SPL; z++) {
            float2 v = reinterpret_cast<const float2*>(d_part + (size_t)z * NROWS * XDBL_W)[i];
            s0 += v.x; s1 += v.y;
        }
        reinterpret_cast<float2*>(d_xdbl)[i] = make_float2(s0, s1);
        split2(s0, s1, d_xd_hi[i], d_xd_lo[i]);
    }
}

// ---------------- causal depthwise conv (k=4) + SiLU, 4 channels/thread -----
__global__ void __launch_bounds__(256)
conv_silu_kernel(const float* __restrict__ conv_w, const float* __restrict__ conv_b)
{
    int i = blockIdx.x * blockDim.x + threadIdx.x;       // NROWS * DINNER / 4
    int rowid = i >> 9;                                   // DINNER/4 = 512
    int dd    = (i & 511) << 2;
    int l     = rowid & (LL - 1);
    const float* base = d_xz + (size_t)rowid * (2 * DINNER) + dd;

    float4 w0 = *(const float4*)(conv_w + (dd + 0) * 4);
    float4 w1 = *(const float4*)(conv_w + (dd + 1) * 4);
    float4 w2 = *(const float4*)(conv_w + (dd + 2) * 4);
    float4 w3 = *(const float4*)(conv_w + (dd + 3) * 4);
    float4 bv = *(const float4*)(conv_b + dd);

    const float4 z4 = make_float4(0.f, 0.f, 0.f, 0.f);
    float4 x0  = *(const float4*)(base);
    float4 xm1 = (l >= 1) ? *(const float4*)(base - 1 * (2 * DINNER)) : z4;
    float4 xm2 = (l >= 2) ? *(const float4*)(base - 2 * (2 * DINNER)) : z4;
    float4 xm3 = (l >= 3) ? *(const float4*)(base - 3 * (2 * DINNER)) : z4;

    float a0 = bv.x + w0.x * xm3.x + w0.y * xm2.x + w0.z * xm1.x + w0.w * x0.x;
    float a1 = bv.y + w1.x * xm3.y + w1.y * xm2.y + w1.z * xm1.y + w1.w * x0.y;
    float a2 = bv.z + w2.x * xm3.z + w2.y * xm2.z + w2.z * xm1.z + w2.w * x0.z;
    float a3 = bv.w + w3.x * xm3.w + w3.y * xm2.w + w3.z * xm1.w + w3.w * x0.w;

    a0 = silu_f(a0); a1 = silu_f(a1); a2 = silu_f(a2); a3 = silu_f(a3);

    *(float4*)(d_xs + (size_t)rowid * DINNER + dd) = make_float4(a0, a1, a2, a3);

    uint32_t h0, l0, h1, l1;
    split2(a0, a1, h0, l0);
    split2(a2, a3, h1, l1);
    size_t o = (size_t)rowid * (DINNER / 2) + (dd >> 1);
    d_xs_hi[o] = h0; d_xs_lo[o] = l0;
    d_xs_hi[o + 1] = h1; d_xs_lo[o + 1] = l1;
}

// ---------------- chunked selective scan: thread per (b, d) -----------------
// a_s = exp(dt * A[d,s]); with A[d,s] == -(s+1) (verified per-thread) this is
// exp(-dt)^(s+1) built from 1 MUFU + ~14 FMULs.
__device__ __forceinline__ void pow_chain(float e, float a[16]) {
    float e2 = e * e, e3 = e2 * e, e4 = e2 * e2;
    a[0] = e;  a[1] = e2; a[2] = e3; a[3] = e4;
    a[4] = e4 * e;  a[5] = e4 * e2; a[6] = e4 * e3; a[7] = e4 * e4;
    float e8 = a[7];
    a[8]  = e8 * e;  a[9]  = e8 * e2; a[10] = e8 * e3; a[11] = e8 * e4;
    a[12] = e8 * a[4]; a[13] = e8 * a[5]; a[14] = e8 * a[6]; a[15] = e8 * e8;
}

__device__ __forceinline__ bool load_A_row(int d, float Ar[16]) {
    float4 A0 = *(const float4*)(d_A + d * 16 + 0);
    float4 A1 = *(const float4*)(d_A + d * 16 + 4);
    float4 A2 = *(const float4*)(d_A + d * 16 + 8);
    float4 A3 = *(const float4*)(d_A + d * 16 + 12);
    Ar[0]=A0.x; Ar[1]=A0.y; Ar[2]=A0.z; Ar[3]=A0.w;
    Ar[4]=A1.x; Ar[5]=A1.y; Ar[6]=A1.z; Ar[7]=A1.w;
    Ar[8]=A2.x; Ar[9]=A2.y; Ar[10]=A2.z; Ar[11]=A2.w;
    Ar[12]=A3.x; Ar[13]=A3.y; Ar[14]=A3.z; Ar[15]=A3.w;
    bool ok = true;
#pragma unroll
    for (int s = 0; s < 16; s++)
        ok = ok && (fabsf(Ar[s] + (float)(s + 1)) <= 1e-4f * (float)(s + 1));
    return ok;
}

// phase 1: per-chunk transition (P, Q) per state
__global__ void __launch_bounds__(256)
scan_phase1_kernel()
{
    int t  = blockIdx.x * 256 + threadIdx.x;     // 0..4095
    int b  = t >> 11;
    int d  = t & (DINNER - 1);
    int ch = blockIdx.y;
    int l0 = ch * CL;

    float Ar[16];
    bool pw = load_A_row(d, Ar);

    const float* dt_p = d_dt + ((size_t)b * LL + l0) * DINNER + d;
    const float* xs_p = d_xs + ((size_t)b * LL + l0) * DINNER + d;
    const float* bc   = d_xdbl + ((size_t)b * LL + l0) * XDBL_W + DTRANK;

    float p[16], q[16];
#pragma unroll
    for (int s = 0; s < 16; s++) { p[s] = 1.f; q[s] = 0.f; }

#pragma unroll 1
    for (int i = 0; i < CL; i++) {
        float dtv = __ldg(dt_p);
        float xv  = __ldg(xs_p);
        float4 B0 = *(const float4*)(bc + 0);
        float4 B1 = *(const float4*)(bc + 4);
        float4 B2 = *(const float4*)(bc + 8);
        float4 B3 = *(const float4*)(bc + 12);
        float Bv[16] = {B0.x,B0.y,B0.z,B0.w, B1.x,B1.y,B1.z,B1.w,
                        B2.x,B2.y,B2.z,B2.w, B3.x,B3.y,B3.z,B3.w};
        float u = dtv * xv;
        float a[16];
        if (pw) {
            pow_chain(__expf(-dtv), a);
        } else {
#pragma unroll
            for (int s = 0; s < 16; s++) a[s] = __expf(dtv * Ar[s]);
        }
#pragma unroll
        for (int s = 0; s < 16; s++) {
            q[s] = fmaf(q[s], a[s], u * Bv[s]);
            p[s] *= a[s];
        }
        dt_p += DINNER; xs_p += DINNER; bc += XDBL_W;
    }

    size_t g0 = (size_t)ch * NGID + ((size_t)b * DINNER + d) * 16;
#pragma unroll
    for (int s = 0; s < 16; s += 4) {
        *(float4*)(d_Pc + g0 + s) = make_float4(p[s], p[s+1], p[s+2], p[s+3]);
        *(float4*)(d_Qc + g0 + s) = make_float4(q[s], q[s+1], q[s+2], q[s+3]);
    }
}

// phase 2: serial combine over chunks -> entry state per chunk
__global__ void __launch_bounds__(256)
scan_phase2_kernel()
{
    int gid = blockIdx.x * blockDim.x + threadIdx.x;
    if (gid >= NGID) return;
    float h = 0.f;
#pragma unroll
    for (int ch = 0; ch < NC; ch++) {
        d_hin[(size_t)ch * NGID + gid] = h;
        h = fmaf(d_Pc[(size_t)ch * NGID + gid], h, d_Qc[(size_t)ch * NGID + gid]);
    }
}

// phase 3: replay chunk from entry state, produce gated y (packed hi/lo)
__global__ void __launch_bounds__(256)
scan_phase3_kernel(const float* __restrict__ Dvec)
{
    int t  = blockIdx.x * 256 + threadIdx.x;
    int b  = t >> 11;
    int d  = t & (DINNER - 1);
    int ch = blockIdx.y;
    int l0 = ch * CL;

    float Ar[16];
    bool pw = load_A_row(d, Ar);
    float Dv = __ldg(Dvec + d);

    const float* dt_p = d_dt + ((size_t)b * LL + l0) * DINNER + d;
    const float* xs_p = d_xs + ((size_t)b * LL + l0) * DINNER + d;
    const float* z_p  = d_xz + ((size_t)b * LL + l0) * (2 * DINNER) + DINNER + d;
    const float* bc   = d_xdbl + ((size_t)b * LL + l0) * XDBL_W + DTRANK;
    size_t yo = ((size_t)b * LL + l0) * (DINNER / 2) + (d >> 1);

    float h[16];
    {
        size_t g0 = (size_t)ch * NGID + ((size_t)b * DINNER + d) * 16;
#pragma unroll
        for (int s = 0; s < 16; s += 4) {
            float4 v = *(const float4*)(d_hin + g0 + s);
            h[s] = v.x; h[s+1] = v.y; h[s+2] = v.z; h[s+3] = v.w;
        }
    }

#pragma unroll 1
    for (int i = 0; i < CL; i++) {
        float dtv = __ldg(dt_p);
        float xv  = __ldg(xs_p);
        float zv  = __ldg(z_p);
        float4 B0 = *(const float4*)(bc + 0);
        float4 B1 = *(const float4*)(bc + 4);
        float4 B2 = *(const float4*)(bc + 8);
        float4 B3 = *(const float4*)(bc + 12);
        float4 C0 = *(const float4*)(bc + 16);
        float4 C1 = *(const float4*)(bc + 20);
        float4 C2 = *(const float4*)(bc + 24);
        float4 C3 = *(const float4*)(bc + 28);
        float Bv[16] = {B0.x,B0.y,B0.z,B0.w, B1.x,B1.y,B1.z,B1.w,
                        B2.x,B2.y,B2.z,B2.w, B3.x,B3.y,B3.z,B3.w};
        float Cv[16] = {C0.x,C0.y,C0.z,C0.w, C1.x,C1.y,C1.z,C1.w,
                        C2.x,C2.y,C2.z,C2.w, C3.x,C3.y,C3.z,C3.w};
        float u = dtv * xv;
        float a[16];
        if (pw) {
            pow_chain(__expf(-dtv), a);
        } else {
#pragma unroll
            for (int s = 0; s < 16; s++) a[s] = __expf(dtv * Ar[s]);
        }
        float y0 = 0.f, y1 = 0.f, y2 = 0.f, y3 = 0.f;
#pragma unroll
        for (int s = 0; s < 16; s += 4) {
            h[s]   = fmaf(h[s],   a[s],   u * Bv[s]);
            h[s+1] = fmaf(h[s+1], a[s+1], u * Bv[s+1]);
            h[s+2] = fmaf(h[s+2], a[s+2], u * Bv[s+2]);
            h[s+3] = fmaf(h[s+3], a[s+3], u * Bv[s+3]);
            y0 = fmaf(h[s],   Cv[s],   y0);
            y1 = fmaf(h[s+1], Cv[s+1], y1);
            y2 = fmaf(h[s+2], Cv[s+2], y2);
            y3 = fmaf(h[s+3], Cv[s+3], y3);
        }
        float yv = ((y0 + y1) + (y2 + y3) + xv * Dv) * silu_f(zv);
        float yN = __shfl_down_sync(0xffffffffu, yv, 1);
        if ((d & 1) == 0) {
            uint32_t hh, ll;
            split2(yv, yN, hh, ll);
            d_y_hi[yo] = hh; d_y_lo[yo] = ll;
        }
        dt_p += DINNER; xs_p += DINNER; z_p += 2 * DINNER;
        bc += XDBL_W; yo += DINNER / 2;
    }
}

// ---------------- launch ----------------
#define SMEM_128x128 (4 * (2 * 128 + 2 * 128) * 12 * 4)  // 98304 B
#define SMEM_128x96  (4 * (2 * 128 + 2 * 96) * 12 * 4)   // 86016 B

extern "C" void kernel_launch(void* const* d_in, const int* in_sizes, int n_in,
                              void* d_out, int out_size)
{
    const float* x         = (const float*)d_in[0];
    const float* W_in      = (const float*)d_in[1];
    const float* conv_w    = (const float*)d_in[2];
    const float* conv_b    = (const float*)d_in[3];
    const float* W_xp      = (const float*)d_in[4];
    const float* W_dt      = (const float*)d_in[5];
    const float* b_dt      = (const float*)d_in[6];
    const float* A_log     = (const float*)d_in[7];
    const float* Dvec      = (const float*)d_in[8];
    const float* W_out_ssm = (const float*)d_in[9];
    const float* W_out     = (const float*)d_in[10];
    const float* b_out     = (const float*)d_in[11];
    float* out = (float*)d_out;

    float *xz, *xdbl, *dt;
    cudaGetSymbolAddress((void**)&xz,   d_xz);
    cudaGetSymbolAddress((void**)&xdbl, d_xdbl);
    cudaGetSymbolAddress((void**)&dt,   d_dt);
    float* part; cudaGetSymbolAddress((void**)&part, d_part);

    uint32_t *x_hi, *x_lo, *Win_hi, *Win_lo, *Wxp_hi, *Wxp_lo, *Wdt_hi, *Wdt_lo;
    uint32_t *Wos_hi, *Wos_lo, *Wo_hi, *Wo_lo, *xs_hi, *xs_lo, *xd_hi, *xd_lo;
    uint32_t *y_hi, *y_lo, *tmp_hi, *tmp_lo;
    cudaGetSymbolAddress((void**)&x_hi,   d_x_hi);   cudaGetSymbolAddress((void**)&x_lo,   d_x_lo);
    cudaGetSymbolAddress((void**)&Win_hi, d_Win_hi); cudaGetSymbolAddress((void**)&Win_lo, d_Win_lo);
    cudaGetSymbolAddress((void**)&Wxp_hi, d_Wxp_hi); cudaGetSymbolAddress((void**)&Wxp_lo, d_Wxp_lo);
    cudaGetSymbolAddress((void**)&Wdt_hi, d_Wdt_hi); cudaGetSymbolAddress((void**)&Wdt_lo, d_Wdt_lo);
    cudaGetSymbolAddress((void**)&Wos_hi, d_Wos_hi); cudaGetSymbolAddress((void**)&Wos_lo, d_Wos_lo);
    cudaGetSymbolAddress((void**)&Wo_hi,  d_Wo_hi);  cudaGetSymbolAddress((void**)&Wo_lo,  d_Wo_lo);
    cudaGetSymbolAddress((void**)&xs_hi,  d_xs_hi);  cudaGetSymbolAddress((void**)&xs_lo,  d_xs_lo);
    cudaGetSymbolAddress((void**)&xd_hi,  d_xd_hi);  cudaGetSymbolAddress((void**)&xd_lo,  d_xd_lo);
    cudaGetSymbolAddress((void**)&y_hi,   d_y_hi);   cudaGetSymbolAddress((void**)&y_lo,   d_y_lo);
    cudaGetSymbolAddress((void**)&tmp_hi, d_tmp_hi); cudaGetSymbolAddress((void**)&tmp_lo, d_tmp_lo);

    static bool attr_done = false;
    if (!attr_done) {
        cudaFuncSetAttribute(gemm_bf<128,128,0>, cudaFuncAttributeMaxDynamicSharedMemorySize, SMEM_128x128);
        cudaFuncSetAttribute(gemm_bf<128,128,1>, cudaFuncAttributeMaxDynamicSharedMemorySize, SMEM_128x128);
        cudaFuncSetAttribute(gemm_bf<128,128,2>, cudaFuncAttributeMaxDynamicSharedMemorySize, SMEM_128x128);
        cudaFuncSetAttribute(gemm_bf<128,128,3>, cudaFuncAttributeMaxDynamicSharedMemorySize, SMEM_128x128);
        cudaFuncSetAttribute(gemm_bf<128,96,0>,  cudaFuncAttributeMaxDynamicSharedMemorySize, SMEM_128x96);
        attr_done = true;
    }

    // splits + A prep (one kernel)
    split_all_kernel<<<(SPTOT + SPA + 255) / 256, 256>>>(
        x, W_in, W_xp, W_dt, W_out_ssm, W_out, A_log);

    // G1: xz = x @ W_in^T -> [4096,4096] fp32
    gemm_bf<128, 128, 0><<<dim3(2 * DINNER / 128, NROWS / 128, 1), 256, SMEM_128x128>>>(
        x_hi, x_lo, Win_hi, Win_lo, nullptr, xz, nullptr, nullptr,
        DMODEL / 2, DMODEL / 2, DMODEL / 2, 2 * DINNER, 0);

    conv_silu_kernel<<<(NROWS * DINNER / 4) / 256, 256>>>(conv_w, conv_b);

    // G2 split-K: partials[z] = xs @ W_xp^T (chunk z), then reduce
    gemm_bf<128, 96, 0><<<dim3(1, NROWS / 128, G2SPL), 256, SMEM_128x96>>>(
        xs_hi, xs_lo, Wxp_hi, Wxp_lo, nullptr, part, nullptr, nullptr,
        (DINNER / 2) / G2SPL, DINNER / 2, DINNER / 2, XDBL_W, NROWS * XDBL_W);
    g2_reduce_kernel<<<(NROWS * XDBL_W / 2 + 255) / 256, 256>>>();

    // G3: dt = softplus(xdbl[:, :64] @ W_dt^T + b_dt) -> [4096,2048] fp32
    gemm_bf<128, 128, 2><<<dim3(DINNER / 128, NROWS / 128, 1), 256, SMEM_128x128>>>(
        xd_hi, xd_lo, Wdt_hi, Wdt_lo, b_dt, dt, nullptr, nullptr,
        DTRANK / 2, XDBL_W / 2, DTRANK / 2, DINNER, 0);

    // chunked scan: transitions -> combine -> replay with outputs
    scan_phase1_kernel<<<dim3(BB * DINNER / 256, NC), 256>>>();
    scan_phase2_kernel<<<NGID / 256, 256>>>();
    scan_phase3_kernel<<<dim3(BB * DINNER / 256, NC), 256>>>(Dvec);

    // G4: tmp = y @ W_out_ssm^T -> hi/lo packed [4096,512]
    gemm_bf<128, 128, 3><<<dim3(DMODEL / 128, NROWS / 128, 1), 256, SMEM_128x128>>>(
        y_hi, y_lo, Wos_hi, Wos_lo, nullptr, nullptr, tmp_hi, tmp_lo,
        DINNER / 2, DINNER / 2, DINNER / 2, DMODEL / 2, 0);

    // G5: out = tmp @ W_out^T + b_out -> [4096,1024] fp32
    gemm_bf<128, 128, 1><<<dim3(DMODEL / 128, NROWS / 128, 1), 256, SMEM_128x128>>>(
        tmp_hi, tmp_lo, Wo_hi, Wo_lo, b_out, out, nullptr, nullptr,
        DMODEL / 2, DMODEL / 2, DMODEL / 2, DMODEL, 0);
}

// round 9
// speedup vs baseline: 5.1655x; 1.2978x over previous
#include <cuda_runtime.h>
#include <cuda_fp16.h>
#include <cstdint>

// MambaSSMBlock: B=2, L=2048, d_model=1024, d_inner=2048, d_state=16,
// d_conv=4, dt_rank=64
#define BB      2
#define LL      2048
#define DMODEL  1024
#define DINNER  2048
#define DSTATE  16
#define DTRANK  64
#define NROWS   (BB * LL)              // 4096
#define XDBL_W  (DTRANK + 2 * DSTATE)  // 96
#define G2SPL   8                      // split-K chunks for G2
#define NC      32                     // scan chunks along L
#define CL      (LL / NC)              // 64 steps per chunk
#define NGID    (BB * DINNER * DSTATE) // 65536 scan lanes

// ---------------- fp32 scratch ----------------
__device__ float d_xz  [(size_t)NROWS * (2 * DINNER)];
__device__ float d_xs  [(size_t)NROWS * DINNER];
__device__ float d_xdbl[(size_t)NROWS * XDBL_W];
__device__ float d_dt  [(size_t)NROWS * DINNER];
__device__ float d_A   [DINNER * DSTATE];
__device__ float d_part[(size_t)G2SPL * NROWS * XDBL_W];
__device__ float d_Pc  [(size_t)NC * NGID];
__device__ float d_Qc  [(size_t)NC * NGID];
__device__ float d_hin [(size_t)NC * NGID];

// ---------------- packed fp16 scratch (pairs along K) ----------------
// activations: hi only. weights: hi + lo residual.
__device__ uint32_t d_x_hi  [(size_t)NROWS * (DMODEL / 2)];
__device__ uint32_t d_Win_hi[(size_t)(2 * DINNER) * (DMODEL / 2)];
__device__ uint32_t d_Win_lo[(size_t)(2 * DINNER) * (DMODEL / 2)];
__device__ uint32_t d_Wxp_hi[(size_t)XDBL_W * (DINNER / 2)];
__device__ uint32_t d_Wxp_lo[(size_t)XDBL_W * (DINNER / 2)];
__device__ uint32_t d_Wdt_hi[(size_t)DINNER * (DTRANK / 2)];
__device__ uint32_t d_Wdt_lo[(size_t)DINNER * (DTRANK / 2)];
__device__ uint32_t d_Wos_hi[(size_t)DMODEL * (DINNER / 2)];
__device__ uint32_t d_Wos_lo[(size_t)DMODEL * (DINNER / 2)];
__device__ uint32_t d_Wo_hi [(size_t)DMODEL * (DMODEL / 2)];
__device__ uint32_t d_Wo_lo [(size_t)DMODEL * (DMODEL / 2)];
__device__ uint32_t d_xs_hi [(size_t)NROWS * (DINNER / 2)];
__device__ uint32_t d_xd_hi [(size_t)NROWS * (XDBL_W / 2)];
__device__ uint32_t d_y_hi  [(size_t)NROWS * (DINNER / 2)];
__device__ uint32_t d_tmp_hi[(size_t)NROWS * (DMODEL / 2)];

// ---------------- helpers ----------------
__device__ __forceinline__ float silu_f(float v) {
    return v / (1.f + __expf(-v));
}

__device__ __forceinline__ uint32_t pack_h2(float x, float y) {
    __half2 h = __floats2half2_rn(x, y);
    return *reinterpret_cast<uint32_t*>(&h);
}

__device__ __forceinline__ void split2h(float x, float y, uint32_t& hi, uint32_t& lo) {
    __half2 h = __floats2half2_rn(x, y);
    float2 hf = __half22float2(h);
    __half2 l = __floats2half2_rn(x - hf.x, y - hf.y);
    hi = *reinterpret_cast<uint32_t*>(&h);
    lo = *reinterpret_cast<uint32_t*>(&l);
}

__device__ __forceinline__ void mma16(float c[4], const uint32_t a[4], const uint32_t b[2]) {
    asm volatile(
        "mma.sync.aligned.m16n8k16.row.col.f32.f16.f16.f32 "
        "{%0,%1,%2,%3},{%4,%5,%6,%7},{%8,%9},{%0,%1,%2,%3};"
        : "+f"(c[0]), "+f"(c[1]), "+f"(c[2]), "+f"(c[3])
        : "r"(a[0]), "r"(a[1]), "r"(a[2]), "r"(a[3]), "r"(b[0]), "r"(b[1]));
}

__device__ __forceinline__ void ldm_x4(uint32_t r[4], uint32_t addr) {
    asm volatile("ldmatrix.sync.aligned.m8n8.x4.shared.b16 {%0,%1,%2,%3}, [%4];"
                 : "=r"(r[0]), "=r"(r[1]), "=r"(r[2]), "=r"(r[3]) : "r"(addr));
}
__device__ __forceinline__ void ldm_x2(uint32_t r[2], uint32_t addr) {
    asm volatile("ldmatrix.sync.aligned.m8n8.x2.shared.b16 {%0,%1}, [%2];"
                 : "=r"(r[0]), "=r"(r[1]) : "r"(addr));
}
__device__ __forceinline__ void cpa16(uint32_t dst, const void* src) {
    asm volatile("cp.async.cg.shared.global [%0], [%1], 16;" :: "r"(dst), "l"(src));
}
__device__ __forceinline__ void cpa_commit() {
    asm volatile("cp.async.commit_group;");
}
template <int N>
__device__ __forceinline__ void cpa_wait() {
    asm volatile("cp.async.wait_group %0;" :: "n"(N));
}

// ---------------- fused split (+ A prep) ----------------
#define SP0 (NROWS * DMODEL / 2)            // x (hi only)
#define SP1 (2 * DINNER * DMODEL / 2)       // W_in
#define SP2 (XDBL_W * DINNER / 2)           // W_xp
#define SP3 (DINNER * DTRANK / 2)           // W_dt
#define SP4 (DMODEL * DINNER / 2)           // W_out_ssm
#define SP5 (DMODEL * DMODEL / 2)           // W_out
#define SPTOT (SP0 + SP1 + SP2 + SP3 + SP4 + SP5)
#define SPA   (DINNER * DSTATE)

__global__ void __launch_bounds__(256)
split_all_kernel(const float* __restrict__ x, const float* __restrict__ Win,
                 const float* __restrict__ Wxp, const float* __restrict__ Wdt,
                 const float* __restrict__ Wos, const float* __restrict__ Wo,
                 const float* __restrict__ A_log)
{
    int i = blockIdx.x * blockDim.x + threadIdx.x;
    if (i >= SPTOT) {
        int j = i - SPTOT;
        if (j < SPA) d_A[j] = -expf(A_log[j]);
        return;
    }
    const float* src; uint32_t *hi, *lo; int off;
    if (i < SP0)                       { src = x;   hi = d_x_hi;   lo = nullptr;  off = i; }
    else if (i < SP0+SP1)              { src = Win; hi = d_Win_hi; lo = d_Win_lo; off = i - SP0; }
    else if (i < SP0+SP1+SP2)          { src = Wxp; hi = d_Wxp_hi; lo = d_Wxp_lo; off = i - (SP0+SP1); }
    else if (i < SP0+SP1+SP2+SP3)      { src = Wdt; hi = d_Wdt_hi; lo = d_Wdt_lo; off = i - (SP0+SP1+SP2); }
    else if (i < SP0+SP1+SP2+SP3+SP4)  { src = Wos; hi = d_Wos_hi; lo = d_Wos_lo; off = i - (SP0+SP1+SP2+SP3); }
    else                               { src = Wo;  hi = d_Wo_hi;  lo = d_Wo_lo;  off = i - (SP0+SP1+SP2+SP3+SP4); }
    float2 v = reinterpret_cast<const float2*>(src)[off];
    if (lo) {
        uint32_t h, l;
        split2h(v.x, v.y, h, l);
        hi[off] = h; lo[off] = l;
    } else {
        hi[off] = pack_h2(v.x, v.y);
    }
}

// ===== fp16 2-mma GEMM: C = A_hi @ (B_hi + B_lo)^T, 4-stage cp.async ========
// EPI: 0 fp32, 1 fp32+bias, 2 softplus(v+bias), 3 packed fp16 hi.
template<int BM, int BN, int EPI>
__global__ void __launch_bounds__(256, 2)
gemm_hf(const uint32_t* __restrict__ Ah,
        const uint32_t* __restrict__ Bh, const uint32_t* __restrict__ Bl,
        const float* __restrict__ bias, float* __restrict__ C,
        uint32_t* __restrict__ Chi,
        int kpairs, int lda, int ldb, int ldc, int c_chunk_stride)
{
    constexpr int P = 12;                        // smem pitch (words)
    constexpr int STAGE = (BM + 2 * BN) * P;     // words per stage
    constexpr int WARPS_N = 4;
    constexpr int WM = BM / 2, WN = BN / WARPS_N;
    constexpr int MT = WM / 16, NT = WN / 8;

    extern __shared__ __align__(16) uint32_t sm[];
    const uint32_t smu = (uint32_t)__cvta_generic_to_shared(sm);

    const int tid = threadIdx.x;
    const int warp = tid >> 5, lane = tid & 31;
    const int wm = (warp / WARPS_N) * WM;
    const int wn = (warp % WARPS_N) * WN;

    float c[MT][NT][4];
#pragma unroll
    for (int i = 0; i < MT; i++)
#pragma unroll
        for (int j = 0; j < NT; j++)
#pragma unroll
            for (int t = 0; t < 4; t++) c[i][j][t] = 0.f;

    const size_t arow0 = (size_t)blockIdx.y * BM;
    const size_t brow0 = (size_t)blockIdx.x * BN;
    const int kp_base = blockIdx.z * kpairs;
    if (EPI == 0 && c_chunk_stride) C += (size_t)blockIdx.z * c_chunk_stride;

    auto load_stage = [&](int s, int kp) {
        uint32_t base = smu + s * STAGE * 4;
#pragma unroll 1
        for (int i = tid; i < BM * 2; i += 256) {
            int r = i >> 1, cg = (i & 1) * 4;
            cpa16(base + (r * P + cg) * 4, Ah + (arow0 + r) * (size_t)lda + kp + cg);
        }
#pragma unroll 1
        for (int i = tid; i < BN * 2; i += 256) {
            int r = i >> 1, cg = (i & 1) * 4;
            size_t go = (brow0 + r) * (size_t)ldb + kp + cg;
            cpa16(base + (BM * P + r * P + cg) * 4, Bh + go);
            cpa16(base + ((BM + BN) * P + r * P + cg) * 4, Bl + go);
        }
    };

    const int la = lane & 15, lg = lane >> 4;
    const int lb = lane & 7, lbg = (lane >> 3) & 1;

    auto compute_stage = [&](int st) {
        const uint32_t aHi = smu + (st * STAGE) * 4;
        const uint32_t bHi = aHi + BM * P * 4;
        const uint32_t bLo = bHi + BN * P * 4;

        uint32_t ah[MT][4], bh[NT][2], bl[NT][2];
#pragma unroll
        for (int mt = 0; mt < MT; mt++) {
            uint32_t off = ((wm + mt * 16 + la) * P + lg * 4) * 4;
            ldm_x4(ah[mt], aHi + off);
        }
#pragma unroll
        for (int nt = 0; nt < NT; nt++) {
            uint32_t off = ((wn + nt * 8 + lb) * P + lbg * 4) * 4;
            ldm_x2(bh[nt], bHi + off);
            ldm_x2(bl[nt], bLo + off);
        }
#pragma unroll
        for (int mt = 0; mt < MT; mt++)
#pragma unroll
            for (int nt = 0; nt < NT; nt++) {
                mma16(c[mt][nt], ah[mt], bh[nt]);
                mma16(c[mt][nt], ah[mt], bl[nt]);
            }
    };

    const int nk = kpairs / 8;                   // K/16 iterations (even)
    load_stage(0, kp_base);
    load_stage(1, kp_base + 8);
    cpa_commit();

    for (int kt = 0; kt < nk; kt += 2) {
        cpa_wait<0>();
        __syncthreads();
        if (kt + 2 < nk) {
            load_stage((kt + 2) & 3, kp_base + (kt + 2) * 8);
            load_stage((kt + 3) & 3, kp_base + (kt + 3) * 8);
            cpa_commit();
        }
        compute_stage(kt & 3);
        compute_stage((kt + 1) & 3);
    }

    // ---------------- epilogue ----------------
#pragma unroll
    for (int mt = 0; mt < MT; mt++) {
#pragma unroll
        for (int nt = 0; nt < NT; nt++) {
            int m0 = blockIdx.y * BM + wm + mt * 16 + (lane >> 2);
            int n  = blockIdx.x * BN + wn + nt * 8 + 2 * (lane & 3);
            float v0 = c[mt][nt][0], v1 = c[mt][nt][1];
            float v2 = c[mt][nt][2], v3 = c[mt][nt][3];
            if (EPI == 1 || EPI == 2) {
                float2 bv = *(const float2*)(bias + n);
                v0 += bv.x; v1 += bv.y; v2 += bv.x; v3 += bv.y;
            }
            if (EPI == 2) {
                v0 = (v0 > 20.f) ? v0 : log1pf(__expf(v0));
                v1 = (v1 > 20.f) ? v1 : log1pf(__expf(v1));
                v2 = (v2 > 20.f) ? v2 : log1pf(__expf(v2));
                v3 = (v3 > 20.f) ? v3 : log1pf(__expf(v3));
            }
            if (EPI <= 2) {
                *(float2*)(C + (size_t)m0 * ldc + n)       = make_float2(v0, v1);
                *(float2*)(C + (size_t)(m0 + 8) * ldc + n) = make_float2(v2, v3);
            } else {
                Chi[(size_t)m0 * ldc + (n >> 1)]       = pack_h2(v0, v1);
                Chi[(size_t)(m0 + 8) * ldc + (n >> 1)] = pack_h2(v2, v3);
            }
        }
    }
}

// ---------------- G2 split-K reduce ----------------
__global__ void g2_reduce_kernel() {
    int i = blockIdx.x * blockDim.x + threadIdx.x;
    if (i < NROWS * XDBL_W / 2) {
        float s0 = 0.f, s1 = 0.f;
#pragma unroll
        for (int z = 0; z < G2SPL; z++) {
            float2 v = reinterpret_cast<const float2*>(d_part + (size_t)z * NROWS * XDBL_W)[i];
            s0 += v.x; s1 += v.y;
        }
        reinterpret_cast<float2*>(d_xdbl)[i] = make_float2(s0, s1);
        d_xd_hi[i] = pack_h2(s0, s1);
    }
}

// ---------------- causal depthwise conv (k=4) + SiLU, 4 channels/thread -----
__global__ void __launch_bounds__(256)
conv_silu_kernel(const float* __restrict__ conv_w, const float* __restrict__ conv_b)
{
    int i = blockIdx.x * blockDim.x + threadIdx.x;       // NROWS * DINNER / 4
    int rowid = i >> 9;                                   // DINNER/4 = 512
    int dd    = (i & 511) << 2;
    int l     = rowid & (LL - 1);
    const float* base = d_xz + (size_t)rowid * (2 * DINNER) + dd;

    float4 w0 = *(const float4*)(conv_w + (dd + 0) * 4);
    float4 w1 = *(const float4*)(conv_w + (dd + 1) * 4);
    float4 w2 = *(const float4*)(conv_w + (dd + 2) * 4);
    float4 w3 = *(const float4*)(conv_w + (dd + 3) * 4);
    float4 bv = *(const float4*)(conv_b + dd);

    const float4 z4 = make_float4(0.f, 0.f, 0.f, 0.f);
    float4 x0  = *(const float4*)(base);
    float4 xm1 = (l >= 1) ? *(const float4*)(base - 1 * (2 * DINNER)) : z4;
    float4 xm2 = (l >= 2) ? *(const float4*)(base - 2 * (2 * DINNER)) : z4;
    float4 xm3 = (l >= 3) ? *(const float4*)(base - 3 * (2 * DINNER)) : z4;

    float a0 = bv.x + w0.x * xm3.x + w0.y * xm2.x + w0.z * xm1.x + w0.w * x0.x;
    float a1 = bv.y + w1.x * xm3.y + w1.y * xm2.y + w1.z * xm1.y + w1.w * x0.y;
    float a2 = bv.z + w2.x * xm3.z + w2.y * xm2.z + w2.z * xm1.z + w2.w * x0.z;
    float a3 = bv.w + w3.x * xm3.w + w3.y * xm2.w + w3.z * xm1.w + w3.w * x0.w;

    a0 = silu_f(a0); a1 = silu_f(a1); a2 = silu_f(a2); a3 = silu_f(a3);

    *(float4*)(d_xs + (size_t)rowid * DINNER + dd) = make_float4(a0, a1, a2, a3);

    size_t o = (size_t)rowid * (DINNER / 2) + (dd >> 1);
    d_xs_hi[o]     = pack_h2(a0, a1);
    d_xs_hi[o + 1] = pack_h2(a2, a3);
}

// ---------------- chunked selective scan: thread per (b, d) -----------------
__device__ __forceinline__ void pow_chain(float e, float a[16]) {
    float e2 = e * e, e3 = e2 * e, e4 = e2 * e2;
    a[0] = e;  a[1] = e2; a[2] = e3; a[3] = e4;
    a[4] = e4 * e;  a[5] = e4 * e2; a[6] = e4 * e3; a[7] = e4 * e4;
    float e8 = a[7];
    a[8]  = e8 * e;  a[9]  = e8 * e2; a[10] = e8 * e3; a[11] = e8 * e4;
    a[12] = e8 * a[4]; a[13] = e8 * a[5]; a[14] = e8 * a[6]; a[15] = e8 * e8;
}

__device__ __forceinline__ bool load_A_row(int d, float Ar[16]) {
    float4 A0 = *(const float4*)(d_A + d * 16 + 0);
    float4 A1 = *(const float4*)(d_A + d * 16 + 4);
    float4 A2 = *(const float4*)(d_A + d * 16 + 8);
    float4 A3 = *(const float4*)(d_A + d * 16 + 12);
    Ar[0]=A0.x; Ar[1]=A0.y; Ar[2]=A0.z; Ar[3]=A0.w;
    Ar[4]=A1.x; Ar[5]=A1.y; Ar[6]=A1.z; Ar[7]=A1.w;
    Ar[8]=A2.x; Ar[9]=A2.y; Ar[10]=A2.z; Ar[11]=A2.w;
    Ar[12]=A3.x; Ar[13]=A3.y; Ar[14]=A3.z; Ar[15]=A3.w;
    bool ok = true;
#pragma unroll
    for (int s = 0; s < 16; s++)
        ok = ok && (fabsf(Ar[s] + (float)(s + 1)) <= 1e-4f * (float)(s + 1));
    return ok;
}

__global__ void __launch_bounds__(256)
scan_phase1_kernel()
{
    int t  = blockIdx.x * 256 + threadIdx.x;     // 0..4095
    int b  = t >> 11;
    int d  = t & (DINNER - 1);
    int ch = blockIdx.y;
    int l0 = ch * CL;

    float Ar[16];
    bool pw = load_A_row(d, Ar);

    const float* dt_p = d_dt + ((size_t)b * LL + l0) * DINNER + d;
    const float* xs_p = d_xs + ((size_t)b * LL + l0) * DINNER + d;
    const float* bc   = d_xdbl + ((size_t)b * LL + l0) * XDBL_W + DTRANK;

    float p[16], q[16];
#pragma unroll
    for (int s = 0; s < 16; s++) { p[s] = 1.f; q[s] = 0.f; }

#pragma unroll 1
    for (int i = 0; i < CL; i++) {
        float dtv = __ldg(dt_p);
        float xv  = __ldg(xs_p);
        float4 B0 = *(const float4*)(bc + 0);
        float4 B1 = *(const float4*)(bc + 4);
        float4 B2 = *(const float4*)(bc + 8);
        float4 B3 = *(const float4*)(bc + 12);
        float Bv[16] = {B0.x,B0.y,B0.z,B0.w, B1.x,B1.y,B1.z,B1.w,
                        B2.x,B2.y,B2.z,B2.w, B3.x,B3.y,B3.z,B3.w};
        float u = dtv * xv;
        float a[16];
        if (pw) {
            pow_chain(__expf(-dtv), a);
        } else {
#pragma unroll
            for (int s = 0; s < 16; s++) a[s] = __expf(dtv * Ar[s]);
        }
#pragma unroll
        for (int s = 0; s < 16; s++) {
            q[s] = fmaf(q[s], a[s], u * Bv[s]);
            p[s] *= a[s];
        }
        dt_p += DINNER; xs_p += DINNER; bc += XDBL_W;
    }

    size_t g0 = (size_t)ch * NGID + ((size_t)b * DINNER + d) * 16;
#pragma unroll
    for (int s = 0; s < 16; s += 4) {
        *(float4*)(d_Pc + g0 + s) = make_float4(p[s], p[s+1], p[s+2], p[s+3]);
        *(float4*)(d_Qc + g0 + s) = make_float4(q[s], q[s+1], q[s+2], q[s+3]);
    }
}

__global__ void __launch_bounds__(256)
scan_phase2_kernel()
{
    int gid = blockIdx.x * blockDim.x + threadIdx.x;
    if (gid >= NGID) return;
    float h = 0.f;
#pragma unroll
    for (int ch = 0; ch < NC; ch++) {
        d_hin[(size_t)ch * NGID + gid] = h;
        h = fmaf(d_Pc[(size_t)ch * NGID + gid], h, d_Qc[(size_t)ch * NGID + gid]);
    }
}

__global__ void __launch_bounds__(256)
scan_phase3_kernel(const float* __restrict__ Dvec)
{
    int t  = blockIdx.x * 256 + threadIdx.x;
    int b  = t >> 11;
    int d  = t & (DINNER - 1);
    int ch = blockIdx.y;
    int l0 = ch * CL;

    float Ar[16];
    bool pw = load_A_row(d, Ar);
    float Dv = __ldg(Dvec + d);

    const float* dt_p = d_dt + ((size_t)b * LL + l0) * DINNER + d;
    const float* xs_p = d_xs + ((size_t)b * LL + l0) * DINNER + d;
    const float* z_p  = d_xz + ((size_t)b * LL + l0) * (2 * DINNER) + DINNER + d;
    const float* bc   = d_xdbl + ((size_t)b * LL + l0) * XDBL_W + DTRANK;
    size_t yo = ((size_t)b * LL + l0) * (DINNER / 2) + (d >> 1);

    float h[16];
    {
        size_t g0 = (size_t)ch * NGID + ((size_t)b * DINNER + d) * 16;
#pragma unroll
        for (int s = 0; s < 16; s += 4) {
            float4 v = *(const float4*)(d_hin + g0 + s);
            h[s] = v.x; h[s+1] = v.y; h[s+2] = v.z; h[s+3] = v.w;
        }
    }

#pragma unroll 1
    for (int i = 0; i < CL; i++) {
        float dtv = __ldg(dt_p);
        float xv  = __ldg(xs_p);
        float zv  = __ldg(z_p);
        float4 B0 = *(const float4*)(bc + 0);
        float4 B1 = *(const float4*)(bc + 4);
        float4 B2 = *(const float4*)(bc + 8);
        float4 B3 = *(const float4*)(bc + 12);
        float4 C0 = *(const float4*)(bc + 16);
        float4 C1 = *(const float4*)(bc + 20);
        float4 C2 = *(const float4*)(bc + 24);
        float4 C3 = *(const float4*)(bc + 28);
        float Bv[16] = {B0.x,B0.y,B0.z,B0.w, B1.x,B1.y,B1.z,B1.w,
                        B2.x,B2.y,B2.z,B2.w, B3.x,B3.y,B3.z,B3.w};
        float Cv[16] = {C0.x,C0.y,C0.z,C0.w, C1.x,C1.y,C1.z,C1.w,
                        C2.x,C2.y,C2.z,C2.w, C3.x,C3.y,C3.z,C3.w};
        float u = dtv * xv;
        float a[16];
        if (pw) {
            pow_chain(__expf(-dtv), a);
        } else {
#pragma unroll
            for (int s = 0; s < 16; s++) a[s] = __expf(dtv * Ar[s]);
        }
        float y0 = 0.f, y1 = 0.f, y2 = 0.f, y3 = 0.f;
#pragma unroll
        for (int s = 0; s < 16; s += 4) {
            h[s]   = fmaf(h[s],   a[s],   u * Bv[s]);
            h[s+1] = fmaf(h[s+1], a[s+1], u * Bv[s+1]);
            h[s+2] = fmaf(h[s+2], a[s+2], u * Bv[s+2]);
            h[s+3] = fmaf(h[s+3], a[s+3], u * Bv[s+3]);
            y0 = fmaf(h[s],   Cv[s],   y0);
            y1 = fmaf(h[s+1], Cv[s+1], y1);
            y2 = fmaf(h[s+2], Cv[s+2], y2);
            y3 = fmaf(h[s+3], Cv[s+3], y3);
        }
        float yv = ((y0 + y1) + (y2 + y3) + xv * Dv) * silu_f(zv);
        float yN = __shfl_down_sync(0xffffffffu, yv, 1);
        if ((d & 1) == 0) d_y_hi[yo] = pack_h2(yv, yN);
        dt_p += DINNER; xs_p += DINNER; z_p += 2 * DINNER;
        bc += XDBL_W; yo += DINNER / 2;
    }
}

// ---------------- launch ----------------
#define SMEM_H_128x128 (4 * (128 + 2 * 128) * 12 * 4)  // 73728 B
#define SMEM_H_128x96  (4 * (128 + 2 * 96) * 12 * 4)   // 61440 B

extern "C" void kernel_launch(void* const* d_in, const int* in_sizes, int n_in,
                              void* d_out, int out_size)
{
    const float* x         = (const float*)d_in[0];
    const float* W_in      = (const float*)d_in[1];
    const float* conv_w    = (const float*)d_in[2];
    const float* conv_b    = (const float*)d_in[3];
    const float* W_xp      = (const float*)d_in[4];
    const float* W_dt      = (const float*)d_in[5];
    const float* b_dt      = (const float*)d_in[6];
    const float* A_log     = (const float*)d_in[7];
    const float* Dvec      = (const float*)d_in[8];
    const float* W_out_ssm = (const float*)d_in[9];
    const float* W_out     = (const float*)d_in[10];
    const float* b_out     = (const float*)d_in[11];
    float* out = (float*)d_out;

    float *xz, *xdbl, *dt;
    cudaGetSymbolAddress((void**)&xz,   d_xz);
    cudaGetSymbolAddress((void**)&xdbl, d_xdbl);
    cudaGetSymbolAddress((void**)&dt,   d_dt);
    float* part; cudaGetSymbolAddress((void**)&part, d_part);

    uint32_t *x_hi, *Win_hi, *Win_lo, *Wxp_hi, *Wxp_lo, *Wdt_hi, *Wdt_lo;
    uint32_t *Wos_hi, *Wos_lo, *Wo_hi, *Wo_lo, *xs_hi, *xd_hi, *y_hi, *tmp_hi;
    cudaGetSymbolAddress((void**)&x_hi,   d_x_hi);
    cudaGetSymbolAddress((void**)&Win_hi, d_Win_hi); cudaGetSymbolAddress((void**)&Win_lo, d_Win_lo);
    cudaGetSymbolAddress((void**)&Wxp_hi, d_Wxp_hi); cudaGetSymbolAddress((void**)&Wxp_lo, d_Wxp_lo);
    cudaGetSymbolAddress((void**)&Wdt_hi, d_Wdt_hi); cudaGetSymbolAddress((void**)&Wdt_lo, d_Wdt_lo);
    cudaGetSymbolAddress((void**)&Wos_hi, d_Wos_hi); cudaGetSymbolAddress((void**)&Wos_lo, d_Wos_lo);
    cudaGetSymbolAddress((void**)&Wo_hi,  d_Wo_hi);  cudaGetSymbolAddress((void**)&Wo_lo,  d_Wo_lo);
    cudaGetSymbolAddress((void**)&xs_hi,  d_xs_hi);
    cudaGetSymbolAddress((void**)&xd_hi,  d_xd_hi);
    cudaGetSymbolAddress((void**)&y_hi,   d_y_hi);
    cudaGetSymbolAddress((void**)&tmp_hi, d_tmp_hi);

    static bool attr_done = false;
    if (!attr_done) {
        cudaFuncSetAttribute(gemm_hf<128,128,0>, cudaFuncAttributeMaxDynamicSharedMemorySize, SMEM_H_128x128);
        cudaFuncSetAttribute(gemm_hf<128,128,1>, cudaFuncAttributeMaxDynamicSharedMemorySize, SMEM_H_128x128);
        cudaFuncSetAttribute(gemm_hf<128,128,2>, cudaFuncAttributeMaxDynamicSharedMemorySize, SMEM_H_128x128);
        cudaFuncSetAttribute(gemm_hf<128,128,3>, cudaFuncAttributeMaxDynamicSharedMemorySize, SMEM_H_128x128);
        cudaFuncSetAttribute(gemm_hf<128,96,0>,  cudaFuncAttributeMaxDynamicSharedMemorySize, SMEM_H_128x96);
        attr_done = true;
    }

    // splits + A prep (one kernel)
    split_all_kernel<<<(SPTOT + SPA + 255) / 256, 256>>>(
        x, W_in, W_xp, W_dt, W_out_ssm, W_out, A_log);

    // G1: xz = x @ W_in^T -> [4096,4096] fp32
    gemm_hf<128, 128, 0><<<dim3(2 * DINNER / 128, NROWS / 128, 1), 256, SMEM_H_128x128>>>(
        x_hi, Win_hi, Win_lo, nullptr, xz, nullptr,
        DMODEL / 2, DMODEL / 2, DMODEL / 2, 2 * DINNER, 0);

    conv_silu_kernel<<<(NROWS * DINNER / 4) / 256, 256>>>(conv_w, conv_b);

    // G2 split-K: partials[z] = xs @ W_xp^T (chunk z), then reduce
    gemm_hf<128, 96, 0><<<dim3(1, NROWS / 128, G2SPL), 256, SMEM_H_128x96>>>(
        xs_hi, Wxp_hi, Wxp_lo, nullptr, part, nullptr,
        (DINNER / 2) / G2SPL, DINNER / 2, DINNER / 2, XDBL_W, NROWS * XDBL_W);
    g2_reduce_kernel<<<(NROWS * XDBL_W / 2 + 255) / 256, 256>>>();

    // G3: dt = softplus(xdbl[:, :64] @ W_dt^T + b_dt) -> [4096,2048] fp32
    gemm_hf<128, 128, 2><<<dim3(DINNER / 128, NROWS / 128, 1), 256, SMEM_H_128x128>>>(
        xd_hi, Wdt_hi, Wdt_lo, b_dt, dt, nullptr,
        DTRANK / 2, XDBL_W / 2, DTRANK / 2, DINNER, 0);

    // chunked scan: transitions -> combine -> replay with outputs
    scan_phase1_kernel<<<dim3(BB * DINNER / 256, NC), 256>>>();
    scan_phase2_kernel<<<NGID / 256, 256>>>();
    scan_phase3_kernel<<<dim3(BB * DINNER / 256, NC), 256>>>(Dvec);

    // G4: tmp = y @ W_out_ssm^T -> packed fp16 [4096,512]
    gemm_hf<128, 128, 3><<<dim3(DMODEL / 128, NROWS / 128, 1), 256, SMEM_H_128x128>>>(
        y_hi, Wos_hi, Wos_lo, nullptr, nullptr, tmp_hi,
        DINNER / 2, DINNER / 2, DINNER / 2, DMODEL / 2, 0);

    // G5: out = tmp @ W_out^T + b_out -> [4096,1024] fp32
    gemm_hf<128, 128, 1><<<dim3(DMODEL / 128, NROWS / 128, 1), 256, SMEM_H_128x128>>>(
        tmp_hi, Wo_hi, Wo_lo, b_out, out, nullptr,
        DMODEL / 2, DMODEL / 2, DMODEL / 2, DMODEL, 0);
}